// round 13
// baseline (speedup 1.0000x reference)
#include <cuda_runtime.h>
#include <cuda_bf16.h>
#include <math.h>
#include <stdint.h>

#define B_ 2
#define T_ 2048
#define C_ 1024
#define H_ 16
#define D_ 64
#define BT_ (B_*T_)
#define RW_ 64
#define RA_ 64
#define RG_ 160
#define RGP_ 192      // RG padded to multiple of 64 (pad cols are zero weights)
#define EPS_ 6.4e-4f  // D * 1e-5
#define RCHUNK 8

// ---------------- packed f32x2 helpers --------------------------------------
__device__ __forceinline__ unsigned long long f32x2_fma(
    unsigned long long a, unsigned long long b, unsigned long long c) {
    unsigned long long d;
    asm("fma.rn.f32x2 %0, %1, %2, %3;" : "=l"(d) : "l"(a), "l"(b), "l"(c));
    return d;
}
__device__ __forceinline__ unsigned long long f32x2_pack(float lo, float hi) {
    unsigned long long d;
    asm("mov.b64 %0, {%1, %2};" : "=l"(d) : "f"(lo), "f"(hi));
    return d;
}
__device__ __forceinline__ float2 f32x2_unpack(unsigned long long v) {
    float lo, hi;
    asm("mov.b64 {%0, %1}, %2;" : "=f"(lo), "=f"(hi) : "l"(v));
    return make_float2(lo, hi);
}
__device__ __forceinline__ uint32_t smem_u32(const void* p) {
    uint32_t a;
    asm("{ .reg .u64 t; cvta.to.shared.u64 t, %1; cvt.u32.u64 %0, t; }"
        : "=r"(a) : "l"(p));
    return a;
}
__device__ __forceinline__ void cp16(uint32_t d, const void* s) {
    asm volatile("cp.async.cg.shared.global [%0], [%1], 16;"
                 :: "r"(d), "l"(s));
}
__device__ __forceinline__ void cp16z(uint32_t d, const void* s, bool ok) {
    int n = ok ? 16 : 0;
    asm volatile("cp.async.cg.shared.global [%0], [%1], 16, %2;"
                 :: "r"(d), "l"(s), "r"(n));
}

// ---------------- scratch (device globals: allocation-free, zero-init) -----
__device__ __nv_bfloat16 g_xrh[BT_*C_], g_xrl[BT_*C_];
__device__ __nv_bfloat16 g_xkh[BT_*C_], g_xkl[BT_*C_];
__device__ __nv_bfloat16 g_xvh[BT_*C_], g_xvl[BT_*C_];
__device__ __nv_bfloat16 g_xwh[BT_*C_], g_xwl[BT_*C_];
__device__ __nv_bfloat16 g_xah[BT_*C_], g_xal[BT_*C_];
__device__ __nv_bfloat16 g_xgh[BT_*C_], g_xgl[BT_*C_];
__device__ __nv_bfloat16 g_preh[BT_*C_], g_prel[BT_*C_];
__device__ __nv_bfloat16 g_wh[4][C_*C_], g_wl[4][C_*C_];   // Wr,Wk,Wv,Wo
__device__ __nv_bfloat16 g_wAh[RW_*C_],  g_wAl[RW_*C_];
__device__ __nv_bfloat16 g_aAh[RA_*C_],  g_aAl[RA_*C_];
__device__ __nv_bfloat16 g_gAh[RGP_*C_], g_gAl[RGP_*C_];   // rows 160..191 = 0
__device__ __nv_bfloat16 g_wBh[C_*RW_],  g_wBl[C_*RW_];
__device__ __nv_bfloat16 g_aBh[C_*RA_],  g_aBl[C_*RA_];
__device__ __nv_bfloat16 g_gBh[C_*RGP_], g_gBl[C_*RGP_];   // k 160..191 = 0
__device__ __nv_bfloat16 g_w1h[BT_*RW_],  g_w1l[BT_*RW_];
__device__ __nv_bfloat16 g_a1h[BT_*RA_],  g_a1l[BT_*RA_];
__device__ __nv_bfloat16 g_g1h[BT_*RGP_], g_g1l[BT_*RGP_];
__device__ float g_r [BT_*C_];
__device__ float g_k [BT_*C_];
__device__ float g_v [BT_*C_];
__device__ float g_decay[BT_*C_];
__device__ float g_a [BT_*C_];
__device__ float g_g [BT_*C_];
__device__ float g_ain[BT_*C_];
__device__ float g_bin[BT_*C_];
__device__ float g_o [BT_*C_];
__device__ float g_w0[C_];

// ---------------- fp32 -> bf16 hi/lo split helpers --------------------------
__device__ __forceinline__ void split4(float4 m, uint2& hi, uint2& lo) {
    __nv_bfloat16 h0 = __float2bfloat16_rn(m.x);
    __nv_bfloat16 h1 = __float2bfloat16_rn(m.y);
    __nv_bfloat16 h2 = __float2bfloat16_rn(m.z);
    __nv_bfloat16 h3 = __float2bfloat16_rn(m.w);
    __nv_bfloat16 l0 = __float2bfloat16_rn(m.x - __bfloat162float(h0));
    __nv_bfloat16 l1 = __float2bfloat16_rn(m.y - __bfloat162float(h1));
    __nv_bfloat16 l2 = __float2bfloat16_rn(m.z - __bfloat162float(h2));
    __nv_bfloat16 l3 = __float2bfloat16_rn(m.w - __bfloat162float(h3));
    __nv_bfloat162 ph0 = __halves2bfloat162(h0, h1);
    __nv_bfloat162 ph1 = __halves2bfloat162(h2, h3);
    __nv_bfloat162 pl0 = __halves2bfloat162(l0, l1);
    __nv_bfloat162 pl1 = __halves2bfloat162(l2, l3);
    hi.x = *reinterpret_cast<uint32_t*>(&ph0);
    hi.y = *reinterpret_cast<uint32_t*>(&ph1);
    lo.x = *reinterpret_cast<uint32_t*>(&pl0);
    lo.y = *reinterpret_cast<uint32_t*>(&pl1);
}
__device__ __forceinline__ uint32_t pack_bf2(float a, float b, uint32_t& lov) {
    __nv_bfloat16 h0 = __float2bfloat16_rn(a), h1 = __float2bfloat16_rn(b);
    __nv_bfloat16 l0 = __float2bfloat16_rn(a - __bfloat162float(h0));
    __nv_bfloat16 l1 = __float2bfloat16_rn(b - __bfloat162float(h1));
    __nv_bfloat162 hh = __halves2bfloat162(h0, h1);
    __nv_bfloat162 ll = __halves2bfloat162(l0, l1);
    lov = *reinterpret_cast<uint32_t*>(&ll);
    return *reinterpret_cast<uint32_t*>(&hh);
}

// ---------------- weight conversion: fp32 -> bf16 hi/lo ---------------------
struct WcJob { const float* src; __nv_bfloat16 *h, *l; int n; };
struct WcJobs { WcJob j[9]; };
__global__ void wconv_kernel(WcJobs jobs)
{
    WcJob jb = jobs.j[blockIdx.y];
    int i = (blockIdx.x * blockDim.x + threadIdx.x) * 4;
    if (i >= jb.n) return;
    float4 v = *(const float4*)(jb.src + i);
    uint2 hi, lo;
    split4(v, hi, lo);
    *(uint2*)(jb.h + i) = hi;
    *(uint2*)(jb.l + i) = lo;
}
// gB: [C_,160] -> [C_,192] with zero K-pad (pad never written; zero-init)
__global__ void wpad_kernel(const float* __restrict__ src,
                            __nv_bfloat16* __restrict__ h,
                            __nv_bfloat16* __restrict__ l)
{
    int i = (blockIdx.x * blockDim.x + threadIdx.x) * 4;
    if (i >= C_*RGP_) return;
    int row = i / RGP_, col = i % RGP_;
    if (col >= RG_) return;
    float4 v = *(const float4*)(src + row*RG_ + col);
    uint2 hi, lo;
    split4(v, hi, lo);
    *(uint2*)(h + i) = hi;
    *(uint2*)(l + i) = lo;
}

// ---------------- token-shift mixing: all 6 emitted as bf16 hi/lo -----------
__global__ void mix_kernel(const float* __restrict__ x,
    const float* __restrict__ cr, const float* __restrict__ cw,
    const float* __restrict__ ck, const float* __restrict__ cv,
    const float* __restrict__ ca, const float* __restrict__ cg)
{
    int i = blockIdx.x * blockDim.x + threadIdx.x;
    if (i >= BT_*C_/4) return;
    int idx = i * 4;
    int c  = idx & (C_-1);
    int bt = idx >> 10;
    int t  = bt & (T_-1);
    float4 xv = *(const float4*)(x + idx);
    float4 xs = make_float4(0.f,0.f,0.f,0.f);
    if (t) xs = *(const float4*)(x + idx - C_);
    float4 d = make_float4(xs.x-xv.x, xs.y-xv.y, xs.z-xv.z, xs.w-xv.w);
    float4 m; uint2 hi, lo;
#define MIXS(cf, ah, al) { float4 cc = *(const float4*)((cf)+c); \
    m = make_float4(xv.x + d.x*cc.x, xv.y + d.y*cc.y, \
                    xv.z + d.z*cc.z, xv.w + d.w*cc.w); \
    split4(m, hi, lo); \
    *(uint2*)((ah) + idx) = hi; *(uint2*)((al) + idx) = lo; }
    MIXS(cr, g_xrh, g_xrl)
    MIXS(ck, g_xkh, g_xkl)
    MIXS(cv, g_xvh, g_xvl)
    MIXS(cw, g_xwh, g_xwl)
    MIXS(ca, g_xah, g_xal)
    MIXS(cg, g_xgh, g_xgl)
#undef MIXS
}

// ---------------- w0 = base + cumsum(softplus(delta)) ----------------------
__global__ void w0_kernel(const float* __restrict__ base,
                          const float* __restrict__ delta)
{
    __shared__ float s[C_];
    int tid = threadIdx.x;
    float v = 0.f;
    if (tid > 0) {
        float d = delta[tid-1];
        v = (d > 20.f) ? d : log1pf(expf(d));
    }
    s[tid] = v;
    __syncthreads();
    for (int off = 1; off < C_; off <<= 1) {
        float t = (tid >= off) ? s[tid-off] : 0.f;
        __syncthreads();
        s[tid] += t;
        __syncthreads();
    }
    g_w0[tid] = base[0] + s[tid];
}

// ================ HMMA bf16-split GEMM (512 thr, k-chunk 64, 2 stages) ======
// C[M,N] = act(A[M,K]*(B[N,K])^T [+bias]); A,B as bf16 hi/lo. K % 64 == 0.
// acts: 0 none->f32 | 1 tanh->bf16split | 2 sigmoid->bf16split |
//       3 decay(w0+bias)->f32 | 5 sigmoid(+bias)->f32 | 6 none->bf16split
struct HJob { const __nv_bfloat16 *Ah, *Al, *Bh, *Bl;
              float* Cf; __nv_bfloat16 *Ch, *Cl;
              const float* bias; int N, K, act; };
struct HJobs { HJob j[3]; };

#define LDK4 72
#define AROWS 256
#define ASZ4 (AROWS*LDK4)

__device__ __forceinline__ void ldm_x4(uint32_t addr, uint32_t r[4]) {
    asm volatile("ldmatrix.sync.aligned.m8n8.x4.shared.b16 {%0,%1,%2,%3}, [%4];"
        : "=r"(r[0]), "=r"(r[1]), "=r"(r[2]), "=r"(r[3]) : "r"(addr));
}
__device__ __forceinline__ void ldm_x2(uint32_t addr, uint32_t r[2]) {
    asm volatile("ldmatrix.sync.aligned.m8n8.x2.shared.b16 {%0,%1}, [%2];"
        : "=r"(r[0]), "=r"(r[1]) : "r"(addr));
}
__device__ __forceinline__ void mma_bf16(float* d, const uint32_t* a,
                                         const uint32_t* b) {
    asm volatile("mma.sync.aligned.m16n8k16.row.col.f32.bf16.bf16.f32 "
        "{%0,%1,%2,%3}, {%4,%5,%6,%7}, {%8,%9}, {%0,%1,%2,%3};"
        : "+f"(d[0]), "+f"(d[1]), "+f"(d[2]), "+f"(d[3])
        : "r"(a[0]), "r"(a[1]), "r"(a[2]), "r"(a[3]), "r"(b[0]), "r"(b[1]));
}

__device__ __forceinline__ void emit2(const HJob& jb, int row, int col,
                                      float v0, float v1)
{
    size_t idx = (size_t)row * jb.N + col;
    int act = jb.act;
    if (act == 0) {
        *(float2*)(jb.Cf + idx) = make_float2(v0, v1);
    } else if (act == 3) {
        float t0 = g_w0[col]   + v0 + jb.bias[col];
        float t1 = g_w0[col+1] + v1 + jb.bias[col+1];
        float n0 = -t0, n1 = -t1;
        float s0 = (n0 > 20.f) ? n0 : log1pf(expf(n0));
        float s1 = (n1 > 20.f) ? n1 : log1pf(expf(n1));
        *(float2*)(jb.Cf + idx) =
            make_float2(expf(-expf(-s0 - 0.5f)), expf(-expf(-s1 - 0.5f)));
    } else if (act == 5) {
        float y0 = 1.f / (1.f + expf(-(v0 + jb.bias[col])));
        float y1 = 1.f / (1.f + expf(-(v1 + jb.bias[col+1])));
        *(float2*)(jb.Cf + idx) = make_float2(y0, y1);
    } else {
        if (act == 1) { v0 = tanhf(v0); v1 = tanhf(v1); }
        else if (act == 2) {
            v0 = 1.f / (1.f + expf(-v0));
            v1 = 1.f / (1.f + expf(-v1));
        }
        uint32_t lov;
        uint32_t hiv = pack_bf2(v0, v1, lov);
        *(uint32_t*)(jb.Ch + idx) = hiv;
        *(uint32_t*)(jb.Cl + idx) = lov;
    }
}

template<int NT>
__global__ void __launch_bounds__(512, 1) hg4_kernel(HJobs jobs)
{
    HJob jb = jobs.j[blockIdx.z];
    const int N = jb.N, K = jb.K;
    const int m0 = blockIdx.y * AROWS;
    const int n0 = blockIdx.x * NT;
    if (n0 >= N) return;

    constexpr int BSZ  = NT * LDK4;
    constexpr int STGE = 2*ASZ4 + 2*BSZ;          // elems per stage
    constexpr int MTt  = (NT == 128) ? 4 : 2;

    extern __shared__ __nv_bfloat16 sm4[];
    uint32_t s0 = smem_u32(sm4);

    int tid  = threadIdx.x;
    int wid  = tid >> 5;
    int lane = tid & 31;
    int wm, wn;
    if (NT == 128) { wm = (wid & 3) * 64; wn = (wid >> 2) * 32; }
    else           { wm = (wid & 7) * 32; wn = (wid >> 3) * 32; }

    // A loaders: 256 rows x 2 half-chunks (32 cols = 4 cp16 per matrix)
    int alr = tid >> 1, alseg = tid & 1;
    const __nv_bfloat16* sAh = jb.Ah + (size_t)(m0 + alr) * K + alseg * 32;
    const __nv_bfloat16* sAl = jb.Al + (size_t)(m0 + alr) * K + alseg * 32;
    uint32_t aoff = (alr * LDK4 + alseg * 32) * 2;

    // B loaders: NT rows x 4 quarter-chunks (16 cols = 2 cp16 per matrix)
    bool bthr = tid < NT*4;
    int brow = (tid >> 2) & (NT-1), bseg = tid & 3;
    bool bok = bthr && ((n0 + brow) < N);
    const __nv_bfloat16* sBh = jb.Bh + (size_t)(n0 + brow) * K + bseg * 16;
    const __nv_bfloat16* sBl = jb.Bl + (size_t)(n0 + brow) * K + bseg * 16;
    uint32_t boff = (2*ASZ4 + brow * LDK4 + bseg * 16) * 2;

    float acc[MTt][4][4];
#pragma unroll
    for (int i = 0; i < MTt; i++)
#pragma unroll
        for (int j = 0; j < 4; j++)
#pragma unroll
            for (int q = 0; q < 4; q++) acc[i][j][q] = 0.f;

    uint32_t rowA = (lane & 15) * (LDK4*2);
    uint32_t colA = (lane >> 4) * 16;
    uint32_t rowB = (lane & 7)  * (LDK4*2);
    uint32_t colB = ((lane >> 3) & 1) * 16;

    const int ncit = K >> 6;   // K % 64 == 0

#define HG4_ISSUE(c, st) do { \
        uint32_t dbase = s0 + (uint32_t)(st) * (STGE*2); \
        int adv = (c) * 64; \
        cp16(dbase + aoff,               sAh + adv); \
        cp16(dbase + aoff + 16,          sAh + adv + 8); \
        cp16(dbase + aoff + 32,          sAh + adv + 16); \
        cp16(dbase + aoff + 48,          sAh + adv + 24); \
        cp16(dbase + ASZ4*2 + aoff,      sAl + adv); \
        cp16(dbase + ASZ4*2 + aoff + 16, sAl + adv + 8); \
        cp16(dbase + ASZ4*2 + aoff + 32, sAl + adv + 16); \
        cp16(dbase + ASZ4*2 + aoff + 48, sAl + adv + 24); \
        if (bthr) { \
            cp16z(dbase + boff,              sBh + adv,     bok); \
            cp16z(dbase + boff + 16,         sBh + adv + 8, bok); \
            cp16z(dbase + BSZ*2 + boff,      sBl + adv,     bok); \
            cp16z(dbase + BSZ*2 + boff + 16, sBl + adv + 8, bok); \
        } \
        asm volatile("cp.async.commit_group;"); \
    } while (0)

    HG4_ISSUE(0, 0);

    for (int c = 0; c < ncit; c++) {
        asm volatile("cp.async.wait_group 0;");   // chunk c arrived
        __syncthreads();                          // stage (c+1)&1 fully drained
        if (c + 1 < ncit)
            HG4_ISSUE(c + 1, (c + 1) & 1);        // overlaps compute below

        uint32_t sb    = s0 + (uint32_t)(c & 1) * (STGE*2);
        uint32_t sAh_b = sb;
        uint32_t sAl_b = sb + ASZ4*2;
        uint32_t sBh_b = sb + 2*ASZ4*2;
        uint32_t sBl_b = sb + (2*ASZ4 + BSZ)*2;

#pragma unroll
        for (int ks = 0; ks < 4; ks++) {
            uint32_t bfh[4][2], bfl[4][2];
#pragma unroll
            for (int nt = 0; nt < 4; nt++) {
                uint32_t bo = (wn + nt*8) * (LDK4*2) + rowB + ks*32 + colB;
                ldm_x2(sBh_b + bo, bfh[nt]);
                ldm_x2(sBl_b + bo, bfl[nt]);
            }
#pragma unroll
            for (int mt = 0; mt < MTt; mt++) {
                uint32_t afh[4], afl[4];
                uint32_t ao = (wm + mt*16) * (LDK4*2) + rowA + ks*32 + colA;
                ldm_x4(sAh_b + ao, afh);
                ldm_x4(sAl_b + ao, afl);
#pragma unroll
                for (int nt = 0; nt < 4; nt++) {
                    mma_bf16(acc[mt][nt], afh, bfh[nt]);
                    mma_bf16(acc[mt][nt], afh, bfl[nt]);
                    mma_bf16(acc[mt][nt], afl, bfh[nt]);
                }
            }
        }
    }
#undef HG4_ISSUE

    int g = lane >> 2, tg = lane & 3;
#pragma unroll
    for (int mt = 0; mt < MTt; mt++) {
#pragma unroll
        for (int nt = 0; nt < 4; nt++) {
            int cb = n0 + wn + nt*8 + 2*tg;
            if (NT == 64 && cb >= N) continue;
            int r0 = m0 + wm + mt*16 + g;
            emit2(jb, r0,     cb, acc[mt][nt][0], acc[mt][nt][1]);
            emit2(jb, r0 + 8, cb, acc[mt][nt][2], acc[mt][nt][3]);
        }
    }
}

#define HS4_128 ((2*ASZ4 + 2*128*LDK4) * 2 * 2)
#define HS4_64  ((2*ASZ4 + 2*64*LDK4)  * 2 * 2)

// ---------------- kk normalize / a_in / b_in / k update --------------------
__global__ void kk_kernel(const float* __restrict__ kkc,
                          const float* __restrict__ kac)
{
    int gid  = blockIdx.x * blockDim.x + threadIdx.x;
    int lane = gid & 31;
    int grp  = gid >> 5;
    if (grp >= BT_*H_) return;
    int bt = grp / H_, h = grp % H_;
    int base = bt * C_ + h * D_;
    int c0   = h * D_;

    float k0v = g_k[base + lane],      k1v = g_k[base + 32 + lane];
    float a0  = g_a[base + lane],      a1  = g_a[base + 32 + lane];
    float kk0 = k0v * kkc[c0 + lane],  kk1 = k1v * kkc[c0 + 32 + lane];

    float ss = kk0*kk0 + kk1*kk1;
#pragma unroll
    for (int o = 16; o; o >>= 1) ss += __shfl_xor_sync(0xffffffffu, ss, o);
    float inv = 1.f / fmaxf(sqrtf(ss), 1e-12f);
    kk0 *= inv; kk1 *= inv;

    g_ain[base + lane]      = -kk0;
    g_ain[base + 32 + lane] = -kk1;
    g_bin[base + lane]      = kk0 * a0;
    g_bin[base + 32 + lane] = kk1 * a1;
    g_k[base + lane]        = k0v * (1.f + (a0 - 1.f) * kac[c0 + lane]);
    g_k[base + 32 + lane]   = k1v * (1.f + (a1 - 1.f) * kac[c0 + 32 + lane]);
}

// ---------------- RWKV-7 recurrence (v5: 64 blocks, 32 rows, cp=4) ----------
// Thread owns S[row, cp*16 .. cp*16+15] (8 f32x2). Reductions: 2 shuffles.
__global__ void __launch_bounds__(128, 1) rec_kernel()
{
    int blk = blockIdx.x;            // 0..63
    int bh  = blk >> 1;              // 0..31
    int rb  = blk & 1;               // row half
    int b = bh >> 4, h = bh & 15;
    size_t base = (size_t)b * T_ * C_ + h * D_;

    __shared__ alignas(16) float rsm[2][6][RCHUNK][64];

    int tid = threadIdx.x;           // 0..127
    int row = rb * 32 + (tid >> 2);  // 0..63
    int cp  = tid & 3;
    int c0  = cp * 16;

    // loaders: 6 vecs x RCHUNK steps x 16 quads = 768 float4 / 128 thr
    const float* srcs[6] = { g_r, g_decay, g_k, g_v, g_ain, g_bin };
    const float* gp[6];
    uint32_t sp_[6];
#pragma unroll
    for (int it = 0; it < 6; it++) {
        int f  = tid + it * 128;
        int q  = f & 15;
        int st = (f >> 4) & (RCHUNK-1);
        int vc = f >> 7;
        gp[it]  = srcs[vc] + base + (size_t)st * C_ + q * 4;
        sp_[it] = (uint32_t)((vc * RCHUNK + st) * 64 + q * 4);
    }

    unsigned long long S[8];
#pragma unroll
    for (int i = 0; i < 8; i++) S[i] = 0ull;

    float4 pf[6];
#pragma unroll
    for (int it = 0; it < 6; it++) pf[it] = *(const float4*)gp[it];

    float* smbase = &rsm[0][0][0][0];
    const int NCH = T_ / RCHUNK;
    for (int ch = 0; ch < NCH; ch++) {
        float* buf = smbase + (ch & 1) * (6*RCHUNK*64);
#pragma unroll
        for (int it = 0; it < 6; it++)
            *(float4*)(buf + sp_[it]) = pf[it];
        __syncthreads();
        if (ch + 1 < NCH) {
            size_t adv = (size_t)(ch + 1) * RCHUNK * C_;
#pragma unroll
            for (int it = 0; it < 6; it++)
                pf[it] = *(const float4*)(gp[it] + adv);
        }

        size_t obase = base + (size_t)ch * RCHUNK * C_ + row;
#pragma unroll 2
        for (int s = 0; s < RCHUNK; s++) {
            const float* rv = buf + (0*RCHUNK + s) * 64 + c0;
            const float* wv = buf + (1*RCHUNK + s) * 64 + c0;
            const float* kv = buf + (2*RCHUNK + s) * 64 + c0;
            const float* vv = buf + (3*RCHUNK + s) * 64;
            const float* av = buf + (4*RCHUNK + s) * 64 + c0;
            const float* bv = buf + (5*RCHUNK + s) * 64 + c0;

            ulonglong2 a0 = *(const ulonglong2*)(av);
            ulonglong2 a1 = *(const ulonglong2*)(av + 4);
            ulonglong2 a2 = *(const ulonglong2*)(av + 8);
            ulonglong2 a3 = *(const ulonglong2*)(av + 12);
            // two independent chains -> shorter dependency
            unsigned long long sx = f32x2_fma(S[0], a0.x, 0ull);
            unsigned long long sy = f32x2_fma(S[1], a0.y, 0ull);
            sx = f32x2_fma(S[2], a1.x, sx);
            sy = f32x2_fma(S[3], a1.y, sy);
            sx = f32x2_fma(S[4], a2.x, sx);
            sy = f32x2_fma(S[5], a2.y, sy);
            sx = f32x2_fma(S[6], a3.x, sx);
            sy = f32x2_fma(S[7], a3.y, sy);
            float2 px = f32x2_unpack(sx), py = f32x2_unpack(sy);
            float sa = (px.x + px.y) + (py.x + py.y);
            sa += __shfl_xor_sync(0xffffffffu, sa, 1);
            sa += __shfl_xor_sync(0xffffffffu, sa, 2);

            float vj = vv[row];
            ulonglong2 w0v = *(const ulonglong2*)(wv);
            ulonglong2 w1v = *(const ulonglong2*)(wv + 4);
            ulonglong2 w2v = *(const ulonglong2*)(wv + 8);
            ulonglong2 w3v = *(const ulonglong2*)(wv + 12);
            ulonglong2 b0v = *(const ulonglong2*)(bv);
            ulonglong2 b1v = *(const ulonglong2*)(bv + 4);
            ulonglong2 b2v = *(const ulonglong2*)(bv + 8);
            ulonglong2 b3v = *(const ulonglong2*)(bv + 12);
            ulonglong2 k0v = *(const ulonglong2*)(kv);
            ulonglong2 k1v = *(const ulonglong2*)(kv + 4);
            ulonglong2 k2v = *(const ulonglong2*)(kv + 8);
            ulonglong2 k3v = *(const ulonglong2*)(kv + 12);
            ulonglong2 r0v = *(const ulonglong2*)(rv);
            ulonglong2 r1v = *(const ulonglong2*)(rv + 4);
            ulonglong2 r2v = *(const ulonglong2*)(rv + 8);
            ulonglong2 r3v = *(const ulonglong2*)(rv + 12);

            unsigned long long sa2 = f32x2_pack(sa, sa);
            unsigned long long v2  = f32x2_pack(vj, vj);

            S[0] = f32x2_fma(v2, k0v.x, f32x2_fma(sa2, b0v.x, f32x2_fma(S[0], w0v.x, 0ull)));
            S[1] = f32x2_fma(v2, k0v.y, f32x2_fma(sa2, b0v.y, f32x2_fma(S[1], w0v.y, 0ull)));
            S[2] = f32x2_fma(v2, k1v.x, f32x2_fma(sa2, b1v.x, f32x2_fma(S[2], w1v.x, 0ull)));
            S[3] = f32x2_fma(v2, k1v.y, f32x2_fma(sa2, b1v.y, f32x2_fma(S[3], w1v.y, 0ull)));
            S[4] = f32x2_fma(v2, k2v.x, f32x2_fma(sa2, b2v.x, f32x2_fma(S[4], w2v.x, 0ull)));
            S[5] = f32x2_fma(v2, k2v.y, f32x2_fma(sa2, b2v.y, f32x2_fma(S[5], w2v.y, 0ull)));
            S[6] = f32x2_fma(v2, k3v.x, f32x2_fma(sa2, b3v.x, f32x2_fma(S[6], w3v.x, 0ull)));
            S[7] = f32x2_fma(v2, k3v.y, f32x2_fma(sa2, b3v.y, f32x2_fma(S[7], w3v.y, 0ull)));

            unsigned long long ox = f32x2_fma(S[0], r0v.x, 0ull);
            unsigned long long oy = f32x2_fma(S[1], r0v.y, 0ull);
            ox = f32x2_fma(S[2], r1v.x, ox);
            oy = f32x2_fma(S[3], r1v.y, oy);
            ox = f32x2_fma(S[4], r2v.x, ox);
            oy = f32x2_fma(S[5], r2v.y, oy);
            ox = f32x2_fma(S[6], r3v.x, ox);
            oy = f32x2_fma(S[7], r3v.y, oy);
            float2 qx = f32x2_unpack(ox), qy = f32x2_unpack(oy);
            float o = (qx.x + qx.y) + (qy.x + qy.y);
            o += __shfl_xor_sync(0xffffffffu, o, 1);
            o += __shfl_xor_sync(0xffffffffu, o, 2);
            if (cp == 0) g_o[obase + (size_t)s * C_] = o;
        }
    }
}

// ---------------- GroupNorm + bonus + gate (emits bf16 hi/lo) --------------
__global__ void post_kernel(const float* __restrict__ rk,
                            const float* __restrict__ gnw,
                            const float* __restrict__ gnb)
{
    int gid  = blockIdx.x * blockDim.x + threadIdx.x;
    int lane = gid & 31;
    int grp  = gid >> 5;
    if (grp >= BT_*H_) return;
    int bt = grp / H_, h = grp % H_;
    int base = bt * C_ + h * D_;
    int c0   = h * D_;

    float o0 = g_o[base + lane], o1 = g_o[base + 32 + lane];
    float su = o0 + o1;
    float sq = o0*o0 + o1*o1;
    float r0 = g_r[base + lane], r1 = g_r[base + 32 + lane];
    float k0 = g_k[base + lane], k1 = g_k[base + 32 + lane];
    float bsum = r0*k0*rk[c0 + lane] + r1*k1*rk[c0 + 32 + lane];
#pragma unroll
    for (int o = 16; o; o >>= 1) {
        su   += __shfl_xor_sync(0xffffffffu, su,   o);
        sq   += __shfl_xor_sync(0xffffffffu, sq,   o);
        bsum += __shfl_xor_sync(0xffffffffu, bsum, o);
    }
    float mu  = su / 64.f;
    float var = sq / 64.f - mu * mu;
    float inv = rsqrtf(var + EPS_);

    float v0 = g_v[base + lane], v1 = g_v[base + 32 + lane];
    float on0 = (o0 - mu) * inv * gnw[c0 + lane]      + gnb[c0 + lane];
    float on1 = (o1 - mu) * inv * gnw[c0 + 32 + lane] + gnb[c0 + 32 + lane];
    float p0 = (on0 + bsum * v0) * g_g[base + lane];
    float p1 = (on1 + bsum * v1) * g_g[base + 32 + lane];

    __nv_bfloat16 h0 = __float2bfloat16_rn(p0);
    __nv_bfloat16 h1 = __float2bfloat16_rn(p1);
    g_preh[base + lane]      = h0;
    g_preh[base + 32 + lane] = h1;
    g_prel[base + lane]      = __float2bfloat16_rn(p0 - __bfloat162float(h0));
    g_prel[base + 32 + lane] = __float2bfloat16_rn(p1 - __bfloat162float(h1));
}

// ---------------- host launcher ---------------------------------------------
extern "C" void kernel_launch(void* const* d_in, const int* in_sizes, int n_in,
                              void* d_out, int out_size)
{
    const float* x        = (const float*)d_in[0];
    const float* x_r      = (const float*)d_in[1];
    const float* x_w      = (const float*)d_in[2];
    const float* x_k      = (const float*)d_in[3];
    const float* x_v      = (const float*)d_in[4];
    const float* x_a      = (const float*)d_in[5];
    const float* x_g      = (const float*)d_in[6];
    const float* k_k      = (const float*)d_in[7];
    const float* k_a      = (const float*)d_in[8];
    const float* r_k      = (const float*)d_in[9];
    const float* Wr       = (const float*)d_in[10];
    const float* Wk       = (const float*)d_in[11];
    const float* Wv       = (const float*)d_in[12];
    const float* Wo       = (const float*)d_in[13];
    const float* wA       = (const float*)d_in[14];
    const float* wB       = (const float*)d_in[15];
    const float* wBias    = (const float*)d_in[16];
    const float* aA       = (const float*)d_in[17];
    const float* aB       = (const float*)d_in[18];
    const float* aBias    = (const float*)d_in[19];
    const float* gA       = (const float*)d_in[20];
    const float* gB       = (const float*)d_in[21];
    const float* gnw      = (const float*)d_in[22];
    const float* gnb      = (const float*)d_in[23];
    const float* w0_base  = (const float*)d_in[24];
    const float* w0_delta = (const float*)d_in[25];
    float* out = (float*)d_out;

#define SYM(p, s) cudaGetSymbolAddress((void**)&p, s)
    float *p_r,*p_k,*p_v,*p_dec,*p_a,*p_g;
    __nv_bfloat16 *p_xrh,*p_xrl,*p_xkh,*p_xkl,*p_xvh,*p_xvl;
    __nv_bfloat16 *p_xwh,*p_xwl,*p_xah,*p_xal,*p_xgh,*p_xgl;
    __nv_bfloat16 *p_preh,*p_prel,*p_wh,*p_wl;
    __nv_bfloat16 *p_wAh,*p_wAl,*p_aAh,*p_aAl,*p_gAh,*p_gAl;
    __nv_bfloat16 *p_wBh,*p_wBl,*p_aBh,*p_aBl,*p_gBh,*p_gBl;
    __nv_bfloat16 *p_w1h,*p_w1l,*p_a1h,*p_a1l,*p_g1h,*p_g1l;
    SYM(p_r, g_r); SYM(p_k, g_k); SYM(p_v, g_v);
    SYM(p_dec, g_decay); SYM(p_a, g_a); SYM(p_g, g_g);
    SYM(p_xrh, g_xrh); SYM(p_xrl, g_xrl);
    SYM(p_xkh, g_xkh); SYM(p_xkl, g_xkl);
    SYM(p_xvh, g_xvh); SYM(p_xvl, g_xvl);
    SYM(p_xwh, g_xwh); SYM(p_xwl, g_xwl);
    SYM(p_xah, g_xah); SYM(p_xal, g_xal);
    SYM(p_xgh, g_xgh); SYM(p_xgl, g_xgl);
    SYM(p_preh, g_preh); SYM(p_prel, g_prel);
    SYM(p_wh, g_wh); SYM(p_wl, g_wl);
    SYM(p_wAh, g_wAh); SYM(p_wAl, g_wAl);
    SYM(p_aAh, g_aAh); SYM(p_aAl, g_aAl);
    SYM(p_gAh, g_gAh); SYM(p_gAl, g_gAl);
    SYM(p_wBh, g_wBh); SYM(p_wBl, g_wBl);
    SYM(p_aBh, g_aBh); SYM(p_aBl, g_aBl);
    SYM(p_gBh, g_gBh); SYM(p_gBl, g_gBl);
    SYM(p_w1h, g_w1h); SYM(p_w1l, g_w1l);
    SYM(p_a1h, g_a1h); SYM(p_a1l, g_a1l);
    SYM(p_g1h, g_g1h); SYM(p_g1l, g_g1l);
#undef SYM

    cudaFuncSetAttribute(hg4_kernel<128>,
        cudaFuncAttributeMaxDynamicSharedMemorySize, HS4_128);
    cudaFuncSetAttribute(hg4_kernel<64>,
        cudaFuncAttributeMaxDynamicSharedMemorySize, HS4_64);

    // 0) weights fp32 -> bf16 hi/lo (gB via padded path)
    {
        WcJobs wj;
        wj.j[0] = { Wr, p_wh + 0*C_*C_, p_wl + 0*C_*C_, C_*C_ };
        wj.j[1] = { Wk, p_wh + 1*C_*C_, p_wl + 1*C_*C_, C_*C_ };
        wj.j[2] = { Wv, p_wh + 2*C_*C_, p_wl + 2*C_*C_, C_*C_ };
        wj.j[3] = { Wo, p_wh + 3*C_*C_, p_wl + 3*C_*C_, C_*C_ };
        wj.j[4] = { wA, p_wAh, p_wAl, RW_*C_ };
        wj.j[5] = { aA, p_aAh, p_aAl, RA_*C_ };
        wj.j[6] = { gA, p_gAh, p_gAl, RG_*C_ };   // rows 160..191 stay zero
        wj.j[7] = { wB, p_wBh, p_wBl, C_*RW_ };
        wj.j[8] = { aB, p_aBh, p_aBl, C_*RA_ };
        wconv_kernel<<<dim3(C_*C_/4/256, 9), 256>>>(wj);
        wpad_kernel<<<(C_*RGP_/4 + 255)/256, 256>>>(gB, p_gBh, p_gBl);
    }

    // 1) token-shift mixes -> bf16 hi/lo (all six)
    mix_kernel<<<(BT_*C_/4 + 255)/256, 256>>>(x, x_r, x_w, x_k, x_v, x_a, x_g);

    // 2) w0 scan
    w0_kernel<<<1, C_>>>(w0_base, w0_delta);

    // 3) r/k/v projections
    {
        HJobs hj;
        hj.j[0] = { p_xrh, p_xrl, p_wh + 0*C_*C_, p_wl + 0*C_*C_,
                    p_r, nullptr, nullptr, nullptr, C_, C_, 0 };
        hj.j[1] = { p_xkh, p_xkl, p_wh + 1*C_*C_, p_wl + 1*C_*C_,
                    p_k, nullptr, nullptr, nullptr, C_, C_, 0 };
        hj.j[2] = { p_xvh, p_xvl, p_wh + 2*C_*C_, p_wl + 2*C_*C_,
                    p_v, nullptr, nullptr, nullptr, C_, C_, 0 };
        hg4_kernel<128><<<dim3(C_/128, BT_/AROWS, 3), 512, HS4_128>>>(hj);
    }

    // 4) LoRA stage 1 (NT=64; g padded to N=192, pad cols harmless)
    {
        HJobs hj;
        hj.j[0] = { p_xwh, p_xwl, p_wAh, p_wAl,
                    nullptr, p_w1h, p_w1l, nullptr, RW_,  C_, 1 };  // tanh
        hj.j[1] = { p_xah, p_xal, p_aAh, p_aAl,
                    nullptr, p_a1h, p_a1l, nullptr, RA_,  C_, 6 };  // none
        hj.j[2] = { p_xgh, p_xgl, p_gAh, p_gAl,
                    nullptr, p_g1h, p_g1l, nullptr, RGP_, C_, 2 };  // sigmoid
        hg4_kernel<64><<<dim3(RGP_/64, BT_/AROWS, 3), 512, HS4_64>>>(hj);
    }

    // 5) LoRA stage 2 (K = 64 / 64 / 192; gB K-pad = 0)
    {
        HJobs hj;
        hj.j[0] = { p_w1h, p_w1l, p_wBh, p_wBl,
                    p_dec, nullptr, nullptr, wBias, C_, RW_,  3 };  // decay
        hj.j[1] = { p_a1h, p_a1l, p_aBh, p_aBl,
                    p_a, nullptr, nullptr, aBias,  C_, RA_,  5 };   // sigm+bias
        hj.j[2] = { p_g1h, p_g1l, p_gBh, p_gBl,
                    p_g, nullptr, nullptr, nullptr, C_, RGP_, 0 };
        hg4_kernel<128><<<dim3(C_/128, BT_/AROWS, 3), 512, HS4_128>>>(hj);
    }

    // 6) kk normalize / a_in / b_in / k update
    kk_kernel<<<(BT_*H_*32 + 255)/256, 256>>>(k_k, k_a);

    // 7) sequential recurrence (64 blocks, cp=4)
    rec_kernel<<<64, 128>>>();

    // 8) GroupNorm + bonus + gate (-> bf16 hi/lo)
    post_kernel<<<(BT_*H_*32 + 255)/256, 256>>>(r_k, gnw, gnb);

    // 9) output projection
    {
        HJobs hj;
        hj.j[0] = { p_preh, p_prel, p_wh + 3*C_*C_, p_wl + 3*C_*C_,
                    out, nullptr, nullptr, nullptr, C_, C_, 0 };
        hj.j[1] = hj.j[0];
        hj.j[2] = hj.j[0];
        hg4_kernel<128><<<dim3(C_/128, BT_/AROWS, 1), 512, HS4_128>>>(hj);
    }
}

// round 14
// speedup vs baseline: 1.2573x; 1.2573x over previous
#include <cuda_runtime.h>
#include <cuda_bf16.h>
#include <math.h>
#include <stdint.h>

#define B_ 2
#define T_ 2048
#define C_ 1024
#define H_ 16
#define D_ 64
#define BT_ (B_*T_)
#define RW_ 64
#define RA_ 64
#define RG_ 160
#define EPS_ 6.4e-4f   // D * 1e-5
#define RCHUNK 8

// ---------------- packed f32x2 helpers --------------------------------------
__device__ __forceinline__ unsigned long long f32x2_fma(
    unsigned long long a, unsigned long long b, unsigned long long c) {
    unsigned long long d;
    asm("fma.rn.f32x2 %0, %1, %2, %3;" : "=l"(d) : "l"(a), "l"(b), "l"(c));
    return d;
}
__device__ __forceinline__ unsigned long long f32x2_pack(float lo, float hi) {
    unsigned long long d;
    asm("mov.b64 %0, {%1, %2};" : "=l"(d) : "f"(lo), "f"(hi));
    return d;
}
__device__ __forceinline__ float2 f32x2_unpack(unsigned long long v) {
    float lo, hi;
    asm("mov.b64 {%0, %1}, %2;" : "=f"(lo), "=f"(hi) : "l"(v));
    return make_float2(lo, hi);
}
__device__ __forceinline__ uint32_t smem_u32(const void* p) {
    uint32_t a;
    asm("{ .reg .u64 t; cvta.to.shared.u64 t, %1; cvt.u32.u64 %0, t; }"
        : "=r"(a) : "l"(p));
    return a;
}
__device__ __forceinline__ void cp16(uint32_t d, const void* s) {
    asm volatile("cp.async.cg.shared.global [%0], [%1], 16;"
                 :: "r"(d), "l"(s));
}
__device__ __forceinline__ void cp16z(uint32_t d, const void* s, bool ok) {
    int n = ok ? 16 : 0;
    asm volatile("cp.async.cg.shared.global [%0], [%1], 16, %2;"
                 :: "r"(d), "l"(s), "r"(n));
}

// ---------------- scratch (device globals: allocation-free) ----------------
__device__ __nv_bfloat16 g_xrh[BT_*C_], g_xrl[BT_*C_];
__device__ __nv_bfloat16 g_xkh[BT_*C_], g_xkl[BT_*C_];
__device__ __nv_bfloat16 g_xvh[BT_*C_], g_xvl[BT_*C_];
__device__ __nv_bfloat16 g_xwh[BT_*C_], g_xwl[BT_*C_];
__device__ __nv_bfloat16 g_xah[BT_*C_], g_xal[BT_*C_];
__device__ __nv_bfloat16 g_xgh[BT_*C_], g_xgl[BT_*C_];
__device__ __nv_bfloat16 g_preh[BT_*C_], g_prel[BT_*C_];
__device__ __nv_bfloat16 g_wh[4][C_*C_], g_wl[4][C_*C_];   // Wr,Wk,Wv,Wo
__device__ __nv_bfloat16 g_wAh[RW_*C_], g_wAl[RW_*C_];
__device__ __nv_bfloat16 g_aAh[RA_*C_], g_aAl[RA_*C_];
__device__ __nv_bfloat16 g_gAh[RG_*C_], g_gAl[RG_*C_];
__device__ __nv_bfloat16 g_wBh[C_*RW_], g_wBl[C_*RW_];
__device__ __nv_bfloat16 g_aBh[C_*RA_], g_aBl[C_*RA_];
__device__ __nv_bfloat16 g_gBh[C_*RG_], g_gBl[C_*RG_];
__device__ __nv_bfloat16 g_w1h[BT_*RW_], g_w1l[BT_*RW_];
__device__ __nv_bfloat16 g_a1h[BT_*RA_], g_a1l[BT_*RA_];
__device__ __nv_bfloat16 g_g1h[BT_*RG_], g_g1l[BT_*RG_];
__device__ float g_r [BT_*C_];
__device__ float g_k [BT_*C_];
__device__ float g_v [BT_*C_];
__device__ float g_decay[BT_*C_];
__device__ float g_a [BT_*C_];
__device__ float g_g [BT_*C_];
__device__ float g_ain[BT_*C_];
__device__ float g_bin[BT_*C_];
__device__ float g_o [BT_*C_];
__device__ float g_w0[C_];

// ---------------- fp32 -> bf16 hi/lo split helpers --------------------------
__device__ __forceinline__ void split4(float4 m, uint2& hi, uint2& lo) {
    __nv_bfloat16 h0 = __float2bfloat16_rn(m.x);
    __nv_bfloat16 h1 = __float2bfloat16_rn(m.y);
    __nv_bfloat16 h2 = __float2bfloat16_rn(m.z);
    __nv_bfloat16 h3 = __float2bfloat16_rn(m.w);
    __nv_bfloat16 l0 = __float2bfloat16_rn(m.x - __bfloat162float(h0));
    __nv_bfloat16 l1 = __float2bfloat16_rn(m.y - __bfloat162float(h1));
    __nv_bfloat16 l2 = __float2bfloat16_rn(m.z - __bfloat162float(h2));
    __nv_bfloat16 l3 = __float2bfloat16_rn(m.w - __bfloat162float(h3));
    __nv_bfloat162 ph0 = __halves2bfloat162(h0, h1);
    __nv_bfloat162 ph1 = __halves2bfloat162(h2, h3);
    __nv_bfloat162 pl0 = __halves2bfloat162(l0, l1);
    __nv_bfloat162 pl1 = __halves2bfloat162(l2, l3);
    hi.x = *reinterpret_cast<uint32_t*>(&ph0);
    hi.y = *reinterpret_cast<uint32_t*>(&ph1);
    lo.x = *reinterpret_cast<uint32_t*>(&pl0);
    lo.y = *reinterpret_cast<uint32_t*>(&pl1);
}
__device__ __forceinline__ uint32_t pack_bf2(float a, float b, uint32_t& lov) {
    __nv_bfloat16 h0 = __float2bfloat16_rn(a), h1 = __float2bfloat16_rn(b);
    __nv_bfloat16 l0 = __float2bfloat16_rn(a - __bfloat162float(h0));
    __nv_bfloat16 l1 = __float2bfloat16_rn(b - __bfloat162float(h1));
    __nv_bfloat162 hh = __halves2bfloat162(h0, h1);
    __nv_bfloat162 ll = __halves2bfloat162(l0, l1);
    lov = *reinterpret_cast<uint32_t*>(&ll);
    return *reinterpret_cast<uint32_t*>(&hh);
}

// ---------------- weight conversion: fp32 -> bf16 hi/lo ---------------------
struct WcJob { const float* src; __nv_bfloat16 *h, *l; int n; };
struct WcJobs { WcJob j[10]; };
__global__ void wconv_kernel(WcJobs jobs)
{
    WcJob jb = jobs.j[blockIdx.y];
    int i = (blockIdx.x * blockDim.x + threadIdx.x) * 4;
    if (i >= jb.n) return;
    float4 v = *(const float4*)(jb.src + i);
    uint2 hi, lo;
    split4(v, hi, lo);
    *(uint2*)(jb.h + i) = hi;
    *(uint2*)(jb.l + i) = lo;
}

// ---------------- token-shift mixing: all 6 emitted as bf16 hi/lo -----------
__global__ void mix_kernel(const float* __restrict__ x,
    const float* __restrict__ cr, const float* __restrict__ cw,
    const float* __restrict__ ck, const float* __restrict__ cv,
    const float* __restrict__ ca, const float* __restrict__ cg)
{
    int i = blockIdx.x * blockDim.x + threadIdx.x;
    if (i >= BT_*C_/4) return;
    int idx = i * 4;
    int c  = idx & (C_-1);
    int bt = idx >> 10;
    int t  = bt & (T_-1);
    float4 xv = *(const float4*)(x + idx);
    float4 xs = make_float4(0.f,0.f,0.f,0.f);
    if (t) xs = *(const float4*)(x + idx - C_);
    float4 d = make_float4(xs.x-xv.x, xs.y-xv.y, xs.z-xv.z, xs.w-xv.w);
    float4 m; uint2 hi, lo;
#define MIXS(cf, ah, al) { float4 cc = *(const float4*)((cf)+c); \
    m = make_float4(xv.x + d.x*cc.x, xv.y + d.y*cc.y, \
                    xv.z + d.z*cc.z, xv.w + d.w*cc.w); \
    split4(m, hi, lo); \
    *(uint2*)((ah) + idx) = hi; *(uint2*)((al) + idx) = lo; }
    MIXS(cr, g_xrh, g_xrl)
    MIXS(ck, g_xkh, g_xkl)
    MIXS(cv, g_xvh, g_xvl)
    MIXS(cw, g_xwh, g_xwl)
    MIXS(ca, g_xah, g_xal)
    MIXS(cg, g_xgh, g_xgl)
#undef MIXS
}

// ---------------- w0 = base + cumsum(softplus(delta)) ----------------------
__global__ void w0_kernel(const float* __restrict__ base,
                          const float* __restrict__ delta)
{
    __shared__ float s[C_];
    int tid = threadIdx.x;
    float v = 0.f;
    if (tid > 0) {
        float d = delta[tid-1];
        v = (d > 20.f) ? d : log1pf(expf(d));
    }
    s[tid] = v;
    __syncthreads();
    for (int off = 1; off < C_; off <<= 1) {
        float t = (tid >= off) ? s[tid-off] : 0.f;
        __syncthreads();
        s[tid] += t;
        __syncthreads();
    }
    g_w0[tid] = base[0] + s[tid];
}

// ================ generic HMMA bf16-split GEMM (512 thr, 3-stage async) =====
struct HJob { const __nv_bfloat16 *Ah, *Al, *Bh, *Bl;
              float* Cf; __nv_bfloat16 *Ch, *Cl;
              const float* bias; int N, K, act; };
struct HJobs { HJob j[3]; };

#define LDK 40
#define AROWS 256
#define ASZ2 (AROWS*LDK)

__device__ __forceinline__ void ldm_x4(uint32_t addr, uint32_t r[4]) {
    asm volatile("ldmatrix.sync.aligned.m8n8.x4.shared.b16 {%0,%1,%2,%3}, [%4];"
        : "=r"(r[0]), "=r"(r[1]), "=r"(r[2]), "=r"(r[3]) : "r"(addr));
}
__device__ __forceinline__ void ldm_x2(uint32_t addr, uint32_t r[2]) {
    asm volatile("ldmatrix.sync.aligned.m8n8.x2.shared.b16 {%0,%1}, [%2];"
        : "=r"(r[0]), "=r"(r[1]) : "r"(addr));
}
__device__ __forceinline__ void mma_bf16(float* d, const uint32_t* a,
                                         const uint32_t* b) {
    asm volatile("mma.sync.aligned.m16n8k16.row.col.f32.bf16.bf16.f32 "
        "{%0,%1,%2,%3}, {%4,%5,%6,%7}, {%8,%9}, {%0,%1,%2,%3};"
        : "+f"(d[0]), "+f"(d[1]), "+f"(d[2]), "+f"(d[3])
        : "r"(a[0]), "r"(a[1]), "r"(a[2]), "r"(a[3]), "r"(b[0]), "r"(b[1]));
}

__device__ __forceinline__ void emit2(const HJob& jb, int row, int col,
                                      float v0, float v1)
{
    size_t idx = (size_t)row * jb.N + col;
    int act = jb.act;
    if (act == 0) {
        *(float2*)(jb.Cf + idx) = make_float2(v0, v1);
    } else if (act == 3) {
        float t0 = g_w0[col]   + v0 + jb.bias[col];
        float t1 = g_w0[col+1] + v1 + jb.bias[col+1];
        float n0 = -t0, n1 = -t1;
        float s0 = (n0 > 20.f) ? n0 : log1pf(expf(n0));
        float s1 = (n1 > 20.f) ? n1 : log1pf(expf(n1));
        *(float2*)(jb.Cf + idx) =
            make_float2(expf(-expf(-s0 - 0.5f)), expf(-expf(-s1 - 0.5f)));
    } else if (act == 5) {
        float y0 = 1.f / (1.f + expf(-(v0 + jb.bias[col])));
        float y1 = 1.f / (1.f + expf(-(v1 + jb.bias[col+1])));
        *(float2*)(jb.Cf + idx) = make_float2(y0, y1);
    } else {
        if (act == 1) { v0 = tanhf(v0); v1 = tanhf(v1); }
        else if (act == 2) {
            v0 = 1.f / (1.f + expf(-v0));
            v1 = 1.f / (1.f + expf(-v1));
        }
        uint32_t lov;
        uint32_t hiv = pack_bf2(v0, v1, lov);
        *(uint32_t*)(jb.Ch + idx) = hiv;
        *(uint32_t*)(jb.Cl + idx) = lov;
    }
}

template<int NT>
__global__ void __launch_bounds__(512, 1) hg3_kernel(HJobs jobs)
{
    HJob jb = jobs.j[blockIdx.z];
    const int N = jb.N, K = jb.K;
    const int m0 = blockIdx.y * AROWS;
    const int n0 = blockIdx.x * NT;
    if (n0 >= N) return;

    constexpr int BSZ  = NT * LDK;
    constexpr int STGE = 2*ASZ2 + 2*BSZ;
    constexpr int MTt  = (NT == 128) ? 4 : 2;

    extern __shared__ __nv_bfloat16 sm3[];
    uint32_t s0 = smem_u32(sm3);

    int tid  = threadIdx.x;
    int wid  = tid >> 5;
    int lane = tid & 31;
    int wm, wn;
    if (NT == 128) { wm = (wid & 3) * 64; wn = (wid >> 2) * 32; }
    else           { wm = (wid & 7) * 32; wn = (wid >> 3) * 32; }

    int alr = tid >> 1, alseg = tid & 1;
    const __nv_bfloat16* sAh = jb.Ah + (size_t)(m0 + alr) * K + alseg * 16;
    const __nv_bfloat16* sAl = jb.Al + (size_t)(m0 + alr) * K + alseg * 16;
    uint32_t aoff = (alr * LDK + alseg * 16) * 2;

    bool bthr = tid < NT*2;
    int brow = (tid >> 1) & (NT-1), bseg = tid & 1;
    bool bok = bthr && ((n0 + brow) < N);
    const __nv_bfloat16* sBh = jb.Bh + (size_t)(n0 + brow) * K + bseg * 16;
    const __nv_bfloat16* sBl = jb.Bl + (size_t)(n0 + brow) * K + bseg * 16;
    uint32_t boff = (2*ASZ2 + brow * LDK + bseg * 16) * 2;

    float acc[MTt][4][4];
#pragma unroll
    for (int i = 0; i < MTt; i++)
#pragma unroll
        for (int j = 0; j < 4; j++)
#pragma unroll
            for (int q = 0; q < 4; q++) acc[i][j][q] = 0.f;

    uint32_t rowA = (lane & 15) * (LDK*2);
    uint32_t colA = (lane >> 4) * 16;
    uint32_t rowB = (lane & 7)  * (LDK*2);
    uint32_t colB = ((lane >> 3) & 1) * 16;

    const int ncit = K >> 5;

#define HG3_ISSUE(c, st) do { \
        uint32_t dbase = s0 + (uint32_t)(st) * (STGE*2); \
        int adv = (c) * 32; \
        cp16(dbase + aoff,               sAh + adv); \
        cp16(dbase + aoff + 16,          sAh + adv + 8); \
        cp16(dbase + ASZ2*2 + aoff,      sAl + adv); \
        cp16(dbase + ASZ2*2 + aoff + 16, sAl + adv + 8); \
        if (bthr) { \
            cp16z(dbase + boff,               sBh + adv,     bok); \
            cp16z(dbase + boff + 16,          sBh + adv + 8, bok); \
            cp16z(dbase + BSZ*2 + boff,       sBl + adv,     bok); \
            cp16z(dbase + BSZ*2 + boff + 16,  sBl + adv + 8, bok); \
        } \
        asm volatile("cp.async.commit_group;"); \
    } while (0)

    HG3_ISSUE(0, 0);
    if (ncit > 1) HG3_ISSUE(1, 1);

    int st = 0;
    for (int c = 0; c < ncit; c++) {
        if (c + 1 < ncit)
            asm volatile("cp.async.wait_group 1;");
        else
            asm volatile("cp.async.wait_group 0;");
        __syncthreads();

        if (c + 2 < ncit) {
            int st2 = st + 2; if (st2 >= 3) st2 -= 3;
            HG3_ISSUE(c + 2, st2);
        }

        uint32_t sb    = s0 + (uint32_t)st * (STGE*2);
        uint32_t sAh_b = sb;
        uint32_t sAl_b = sb + ASZ2*2;
        uint32_t sBh_b = sb + 2*ASZ2*2;
        uint32_t sBl_b = sb + (2*ASZ2 + BSZ)*2;

#pragma unroll
        for (int ks = 0; ks < 2; ks++) {
            uint32_t bfh[4][2], bfl[4][2];
#pragma unroll
            for (int nt = 0; nt < 4; nt++) {
                uint32_t bo = (wn + nt*8) * (LDK*2) + rowB + ks*32 + colB;
                ldm_x2(sBh_b + bo, bfh[nt]);
                ldm_x2(sBl_b + bo, bfl[nt]);
            }
#pragma unroll
            for (int mt = 0; mt < MTt; mt++) {
                uint32_t afh[4], afl[4];
                uint32_t ao = (wm + mt*16) * (LDK*2) + rowA + ks*32 + colA;
                ldm_x4(sAh_b + ao, afh);
                ldm_x4(sAl_b + ao, afl);
#pragma unroll
                for (int nt = 0; nt < 4; nt++) {
                    mma_bf16(acc[mt][nt], afh, bfh[nt]);
                    mma_bf16(acc[mt][nt], afh, bfl[nt]);
                    mma_bf16(acc[mt][nt], afl, bfh[nt]);
                }
            }
        }
        if (++st == 3) st = 0;
    }
#undef HG3_ISSUE

    int g = lane >> 2, tg = lane & 3;
#pragma unroll
    for (int mt = 0; mt < MTt; mt++) {
#pragma unroll
        for (int nt = 0; nt < 4; nt++) {
            int cb = n0 + wn + nt*8 + 2*tg;
            if (NT == 64 && cb >= N) continue;
            int r0 = m0 + wm + mt*16 + g;
            emit2(jb, r0,     cb, acc[mt][nt][0], acc[mt][nt][1]);
            emit2(jb, r0 + 8, cb, acc[mt][nt][2], acc[mt][nt][3]);
        }
    }
}

#define HS3_128 ((2*ASZ2 + 2*128*LDK) * 2 * 3)
#define HS3_64  ((2*ASZ2 + 2*64*LDK)  * 2 * 3)

// ---------------- kk normalize / a_in / b_in / k update --------------------
__global__ void kk_kernel(const float* __restrict__ kkc,
                          const float* __restrict__ kac)
{
    int gid  = blockIdx.x * blockDim.x + threadIdx.x;
    int lane = gid & 31;
    int grp  = gid >> 5;
    if (grp >= BT_*H_) return;
    int bt = grp / H_, h = grp % H_;
    int base = bt * C_ + h * D_;
    int c0   = h * D_;

    float k0v = g_k[base + lane],      k1v = g_k[base + 32 + lane];
    float a0  = g_a[base + lane],      a1  = g_a[base + 32 + lane];
    float kk0 = k0v * kkc[c0 + lane],  kk1 = k1v * kkc[c0 + 32 + lane];

    float ss = kk0*kk0 + kk1*kk1;
#pragma unroll
    for (int o = 16; o; o >>= 1) ss += __shfl_xor_sync(0xffffffffu, ss, o);
    float inv = 1.f / fmaxf(sqrtf(ss), 1e-12f);
    kk0 *= inv; kk1 *= inv;

    g_ain[base + lane]      = -kk0;
    g_ain[base + 32 + lane] = -kk1;
    g_bin[base + lane]      = kk0 * a0;
    g_bin[base + 32 + lane] = kk1 * a1;
    g_k[base + lane]        = k0v * (1.f + (a0 - 1.f) * kac[c0 + lane]);
    g_k[base + 32 + lane]   = k1v * (1.f + (a1 - 1.f) * kac[c0 + 32 + lane]);
}

// ---------------- RWKV-7 recurrence (v6: 128 blocks x 64 thr, cp=4) --------
// Block = (b, h, 16-row group); thread owns S[row, cp*16 .. cp*16+15].
// Reductions need only 2 shuffles (4 threads/row).
__global__ void __launch_bounds__(64, 1) rec_kernel()
{
    int blk = blockIdx.x;            // 0..127
    int bh  = blk >> 2;              // 0..31
    int rb  = blk & 3;               // row group
    int b = bh >> 4, h = bh & 15;
    size_t base = (size_t)b * T_ * C_ + h * D_;

    __shared__ alignas(16) float rsm[2][6][RCHUNK][64];

    int tid = threadIdx.x;           // 0..63
    int row = rb * 16 + (tid >> 2);  // global row
    int cp  = tid & 3;
    int c0  = cp * 16;

    // loaders: 6 vecs x RCHUNK steps x 16 quads = 768 float4 / 64 thr = 12 ea
    const float* srcs[6] = { g_r, g_decay, g_k, g_v, g_ain, g_bin };
    const float* gp[12];
    uint32_t sp_[12];
#pragma unroll
    for (int it = 0; it < 12; it++) {
        int f  = tid + it * 64;
        int q  = f & 15;
        int st = (f >> 4) & (RCHUNK-1);
        int vc = f >> 7;
        gp[it]  = srcs[vc] + base + (size_t)st * C_ + q * 4;
        sp_[it] = (uint32_t)((vc * RCHUNK + st) * 64 + q * 4);
    }

    unsigned long long S[8];
#pragma unroll
    for (int i = 0; i < 8; i++) S[i] = 0ull;

    float4 pf[12];
#pragma unroll
    for (int it = 0; it < 12; it++) pf[it] = *(const float4*)gp[it];

    float* smbase = &rsm[0][0][0][0];
    const int NCH = T_ / RCHUNK;
    for (int ch = 0; ch < NCH; ch++) {
        float* buf = smbase + (ch & 1) * (6*RCHUNK*64);
#pragma unroll
        for (int it = 0; it < 12; it++)
            *(float4*)(buf + sp_[it]) = pf[it];
        __syncthreads();
        if (ch + 1 < NCH) {
            size_t adv = (size_t)(ch + 1) * RCHUNK * C_;
#pragma unroll
            for (int it = 0; it < 12; it++)
                pf[it] = *(const float4*)(gp[it] + adv);
        }

        size_t obase = base + (size_t)ch * RCHUNK * C_ + row;
#pragma unroll 2
        for (int s = 0; s < RCHUNK; s++) {
            const float* rv = buf + (0*RCHUNK + s) * 64 + c0;
            const float* wv = buf + (1*RCHUNK + s) * 64 + c0;
            const float* kv = buf + (2*RCHUNK + s) * 64 + c0;
            const float* vv = buf + (3*RCHUNK + s) * 64;
            const float* av = buf + (4*RCHUNK + s) * 64 + c0;
            const float* bv = buf + (5*RCHUNK + s) * 64 + c0;

            ulonglong2 a0 = *(const ulonglong2*)(av);
            ulonglong2 a1 = *(const ulonglong2*)(av + 4);
            ulonglong2 a2 = *(const ulonglong2*)(av + 8);
            ulonglong2 a3 = *(const ulonglong2*)(av + 12);
            unsigned long long sx = f32x2_fma(S[0], a0.x, 0ull);
            unsigned long long sy = f32x2_fma(S[1], a0.y, 0ull);
            sx = f32x2_fma(S[2], a1.x, sx);
            sy = f32x2_fma(S[3], a1.y, sy);
            sx = f32x2_fma(S[4], a2.x, sx);
            sy = f32x2_fma(S[5], a2.y, sy);
            sx = f32x2_fma(S[6], a3.x, sx);
            sy = f32x2_fma(S[7], a3.y, sy);
            float2 px = f32x2_unpack(sx), py = f32x2_unpack(sy);
            float sa = (px.x + px.y) + (py.x + py.y);
            sa += __shfl_xor_sync(0xffffffffu, sa, 1);
            sa += __shfl_xor_sync(0xffffffffu, sa, 2);

            float vj = vv[row];
            ulonglong2 w0v = *(const ulonglong2*)(wv);
            ulonglong2 w1v = *(const ulonglong2*)(wv + 4);
            ulonglong2 w2v = *(const ulonglong2*)(wv + 8);
            ulonglong2 w3v = *(const ulonglong2*)(wv + 12);
            ulonglong2 b0v = *(const ulonglong2*)(bv);
            ulonglong2 b1v = *(const ulonglong2*)(bv + 4);
            ulonglong2 b2v = *(const ulonglong2*)(bv + 8);
            ulonglong2 b3v = *(const ulonglong2*)(bv + 12);
            ulonglong2 k0v = *(const ulonglong2*)(kv);
            ulonglong2 k1v = *(const ulonglong2*)(kv + 4);
            ulonglong2 k2v = *(const ulonglong2*)(kv + 8);
            ulonglong2 k3v = *(const ulonglong2*)(kv + 12);
            ulonglong2 r0v = *(const ulonglong2*)(rv);
            ulonglong2 r1v = *(const ulonglong2*)(rv + 4);
            ulonglong2 r2v = *(const ulonglong2*)(rv + 8);
            ulonglong2 r3v = *(const ulonglong2*)(rv + 12);

            unsigned long long sa2 = f32x2_pack(sa, sa);
            unsigned long long v2  = f32x2_pack(vj, vj);

            S[0] = f32x2_fma(v2, k0v.x, f32x2_fma(sa2, b0v.x, f32x2_fma(S[0], w0v.x, 0ull)));
            S[1] = f32x2_fma(v2, k0v.y, f32x2_fma(sa2, b0v.y, f32x2_fma(S[1], w0v.y, 0ull)));
            S[2] = f32x2_fma(v2, k1v.x, f32x2_fma(sa2, b1v.x, f32x2_fma(S[2], w1v.x, 0ull)));
            S[3] = f32x2_fma(v2, k1v.y, f32x2_fma(sa2, b1v.y, f32x2_fma(S[3], w1v.y, 0ull)));
            S[4] = f32x2_fma(v2, k2v.x, f32x2_fma(sa2, b2v.x, f32x2_fma(S[4], w2v.x, 0ull)));
            S[5] = f32x2_fma(v2, k2v.y, f32x2_fma(sa2, b2v.y, f32x2_fma(S[5], w2v.y, 0ull)));
            S[6] = f32x2_fma(v2, k3v.x, f32x2_fma(sa2, b3v.x, f32x2_fma(S[6], w3v.x, 0ull)));
            S[7] = f32x2_fma(v2, k3v.y, f32x2_fma(sa2, b3v.y, f32x2_fma(S[7], w3v.y, 0ull)));

            unsigned long long ox = f32x2_fma(S[0], r0v.x, 0ull);
            unsigned long long oy = f32x2_fma(S[1], r0v.y, 0ull);
            ox = f32x2_fma(S[2], r1v.x, ox);
            oy = f32x2_fma(S[3], r1v.y, oy);
            ox = f32x2_fma(S[4], r2v.x, ox);
            oy = f32x2_fma(S[5], r2v.y, oy);
            ox = f32x2_fma(S[6], r3v.x, ox);
            oy = f32x2_fma(S[7], r3v.y, oy);
            float2 qx = f32x2_unpack(ox), qy = f32x2_unpack(oy);
            float o = (qx.x + qx.y) + (qy.x + qy.y);
            o += __shfl_xor_sync(0xffffffffu, o, 1);
            o += __shfl_xor_sync(0xffffffffu, o, 2);
            if (cp == 0) g_o[obase + (size_t)s * C_] = o;
        }
    }
}

// ---------------- GroupNorm + bonus + gate (emits bf16 hi/lo) --------------
__global__ void post_kernel(const float* __restrict__ rk,
                            const float* __restrict__ gnw,
                            const float* __restrict__ gnb)
{
    int gid  = blockIdx.x * blockDim.x + threadIdx.x;
    int lane = gid & 31;
    int grp  = gid >> 5;
    if (grp >= BT_*H_) return;
    int bt = grp / H_, h = grp % H_;
    int base = bt * C_ + h * D_;
    int c0   = h * D_;

    float o0 = g_o[base + lane], o1 = g_o[base + 32 + lane];
    float su = o0 + o1;
    float sq = o0*o0 + o1*o1;
    float r0 = g_r[base + lane], r1 = g_r[base + 32 + lane];
    float k0 = g_k[base + lane], k1 = g_k[base + 32 + lane];
    float bsum = r0*k0*rk[c0 + lane] + r1*k1*rk[c0 + 32 + lane];
#pragma unroll
    for (int o = 16; o; o >>= 1) {
        su   += __shfl_xor_sync(0xffffffffu, su,   o);
        sq   += __shfl_xor_sync(0xffffffffu, sq,   o);
        bsum += __shfl_xor_sync(0xffffffffu, bsum, o);
    }
    float mu  = su / 64.f;
    float var = sq / 64.f - mu * mu;
    float inv = rsqrtf(var + EPS_);

    float v0 = g_v[base + lane], v1 = g_v[base + 32 + lane];
    float on0 = (o0 - mu) * inv * gnw[c0 + lane]      + gnb[c0 + lane];
    float on1 = (o1 - mu) * inv * gnw[c0 + 32 + lane] + gnb[c0 + 32 + lane];
    float p0 = (on0 + bsum * v0) * g_g[base + lane];
    float p1 = (on1 + bsum * v1) * g_g[base + 32 + lane];

    __nv_bfloat16 h0 = __float2bfloat16_rn(p0);
    __nv_bfloat16 h1 = __float2bfloat16_rn(p1);
    g_preh[base + lane]      = h0;
    g_preh[base + 32 + lane] = h1;
    g_prel[base + lane]      = __float2bfloat16_rn(p0 - __bfloat162float(h0));
    g_prel[base + 32 + lane] = __float2bfloat16_rn(p1 - __bfloat162float(h1));
}

// ---------------- host launcher ---------------------------------------------
extern "C" void kernel_launch(void* const* d_in, const int* in_sizes, int n_in,
                              void* d_out, int out_size)
{
    const float* x        = (const float*)d_in[0];
    const float* x_r      = (const float*)d_in[1];
    const float* x_w      = (const float*)d_in[2];
    const float* x_k      = (const float*)d_in[3];
    const float* x_v      = (const float*)d_in[4];
    const float* x_a      = (const float*)d_in[5];
    const float* x_g      = (const float*)d_in[6];
    const float* k_k      = (const float*)d_in[7];
    const float* k_a      = (const float*)d_in[8];
    const float* r_k      = (const float*)d_in[9];
    const float* Wr       = (const float*)d_in[10];
    const float* Wk       = (const float*)d_in[11];
    const float* Wv       = (const float*)d_in[12];
    const float* Wo       = (const float*)d_in[13];
    const float* wA       = (const float*)d_in[14];
    const float* wB       = (const float*)d_in[15];
    const float* wBias    = (const float*)d_in[16];
    const float* aA       = (const float*)d_in[17];
    const float* aB       = (const float*)d_in[18];
    const float* aBias    = (const float*)d_in[19];
    const float* gA       = (const float*)d_in[20];
    const float* gB       = (const float*)d_in[21];
    const float* gnw      = (const float*)d_in[22];
    const float* gnb      = (const float*)d_in[23];
    const float* w0_base  = (const float*)d_in[24];
    const float* w0_delta = (const float*)d_in[25];
    float* out = (float*)d_out;

#define SYM(p, s) cudaGetSymbolAddress((void**)&p, s)
    float *p_r,*p_k,*p_v,*p_dec,*p_a,*p_g;
    __nv_bfloat16 *p_xrh,*p_xrl,*p_xkh,*p_xkl,*p_xvh,*p_xvl;
    __nv_bfloat16 *p_xwh,*p_xwl,*p_xah,*p_xal,*p_xgh,*p_xgl;
    __nv_bfloat16 *p_preh,*p_prel,*p_wh,*p_wl;
    __nv_bfloat16 *p_wAh,*p_wAl,*p_aAh,*p_aAl,*p_gAh,*p_gAl;
    __nv_bfloat16 *p_wBh,*p_wBl,*p_aBh,*p_aBl,*p_gBh,*p_gBl;
    __nv_bfloat16 *p_w1h,*p_w1l,*p_a1h,*p_a1l,*p_g1h,*p_g1l;
    SYM(p_r, g_r); SYM(p_k, g_k); SYM(p_v, g_v);
    SYM(p_dec, g_decay); SYM(p_a, g_a); SYM(p_g, g_g);
    SYM(p_xrh, g_xrh); SYM(p_xrl, g_xrl);
    SYM(p_xkh, g_xkh); SYM(p_xkl, g_xkl);
    SYM(p_xvh, g_xvh); SYM(p_xvl, g_xvl);
    SYM(p_xwh, g_xwh); SYM(p_xwl, g_xwl);
    SYM(p_xah, g_xah); SYM(p_xal, g_xal);
    SYM(p_xgh, g_xgh); SYM(p_xgl, g_xgl);
    SYM(p_preh, g_preh); SYM(p_prel, g_prel);
    SYM(p_wh, g_wh); SYM(p_wl, g_wl);
    SYM(p_wAh, g_wAh); SYM(p_wAl, g_wAl);
    SYM(p_aAh, g_aAh); SYM(p_aAl, g_aAl);
    SYM(p_gAh, g_gAh); SYM(p_gAl, g_gAl);
    SYM(p_wBh, g_wBh); SYM(p_wBl, g_wBl);
    SYM(p_aBh, g_aBh); SYM(p_aBl, g_aBl);
    SYM(p_gBh, g_gBh); SYM(p_gBl, g_gBl);
    SYM(p_w1h, g_w1h); SYM(p_w1l, g_w1l);
    SYM(p_a1h, g_a1h); SYM(p_a1l, g_a1l);
    SYM(p_g1h, g_g1h); SYM(p_g1l, g_g1l);
#undef SYM

    cudaFuncSetAttribute(hg3_kernel<128>,
        cudaFuncAttributeMaxDynamicSharedMemorySize, HS3_128);
    cudaFuncSetAttribute(hg3_kernel<64>,
        cudaFuncAttributeMaxDynamicSharedMemorySize, HS3_64);

    // 0) all weights fp32 -> bf16 hi/lo
    {
        WcJobs wj;
        wj.j[0] = { Wr, p_wh + 0*C_*C_, p_wl + 0*C_*C_, C_*C_ };
        wj.j[1] = { Wk, p_wh + 1*C_*C_, p_wl + 1*C_*C_, C_*C_ };
        wj.j[2] = { Wv, p_wh + 2*C_*C_, p_wl + 2*C_*C_, C_*C_ };
        wj.j[3] = { Wo, p_wh + 3*C_*C_, p_wl + 3*C_*C_, C_*C_ };
        wj.j[4] = { wA, p_wAh, p_wAl, RW_*C_ };
        wj.j[5] = { aA, p_aAh, p_aAl, RA_*C_ };
        wj.j[6] = { gA, p_gAh, p_gAl, RG_*C_ };
        wj.j[7] = { wB, p_wBh, p_wBl, C_*RW_ };
        wj.j[8] = { aB, p_aBh, p_aBl, C_*RA_ };
        wj.j[9] = { gB, p_gBh, p_gBl, C_*RG_ };
        wconv_kernel<<<dim3(C_*C_/4/256, 10), 256>>>(wj);
    }

    // 1) token-shift mixes -> bf16 hi/lo (all six)
    mix_kernel<<<(BT_*C_/4 + 255)/256, 256>>>(x, x_r, x_w, x_k, x_v, x_a, x_g);

    // 2) w0 scan
    w0_kernel<<<1, C_>>>(w0_base, w0_delta);

    // 3) r/k/v projections (HMMA 256x128, 3-stage cp.async)
    {
        HJobs hj;
        hj.j[0] = { p_xrh, p_xrl, p_wh + 0*C_*C_, p_wl + 0*C_*C_,
                    p_r, nullptr, nullptr, nullptr, C_, C_, 0 };
        hj.j[1] = { p_xkh, p_xkl, p_wh + 1*C_*C_, p_wl + 1*C_*C_,
                    p_k, nullptr, nullptr, nullptr, C_, C_, 0 };
        hj.j[2] = { p_xvh, p_xvl, p_wh + 2*C_*C_, p_wl + 2*C_*C_,
                    p_v, nullptr, nullptr, nullptr, C_, C_, 0 };
        hg3_kernel<128><<<dim3(C_/128, BT_/AROWS, 3), 512, HS3_128>>>(hj);
    }

    // 4) LoRA stage 1 (NT=64, epilogue emits bf16 hi/lo)
    {
        HJobs hj;
        hj.j[0] = { p_xwh, p_xwl, p_wAh, p_wAl,
                    nullptr, p_w1h, p_w1l, nullptr, RW_, C_, 1 };   // tanh
        hj.j[1] = { p_xah, p_xal, p_aAh, p_aAl,
                    nullptr, p_a1h, p_a1l, nullptr, RA_, C_, 6 };   // none
        hj.j[2] = { p_xgh, p_xgl, p_gAh, p_gAl,
                    nullptr, p_g1h, p_g1l, nullptr, RG_, C_, 2 };   // sigmoid
        hg3_kernel<64><<<dim3((RG_+63)/64, BT_/AROWS, 3), 512, HS3_64>>>(hj);
    }

    // 5) LoRA stage 2 (NT=128, fused epilogues)
    {
        HJobs hj;
        hj.j[0] = { p_w1h, p_w1l, p_wBh, p_wBl,
                    p_dec, nullptr, nullptr, wBias, C_, RW_, 3 };   // decay
        hj.j[1] = { p_a1h, p_a1l, p_aBh, p_aBl,
                    p_a, nullptr, nullptr, aBias, C_, RA_, 5 };     // sigm+bias
        hj.j[2] = { p_g1h, p_g1l, p_gBh, p_gBl,
                    p_g, nullptr, nullptr, nullptr, C_, RG_, 0 };
        hg3_kernel<128><<<dim3(C_/128, BT_/AROWS, 3), 512, HS3_128>>>(hj);
    }

    // 6) kk normalize / a_in / b_in / k update
    kk_kernel<<<(BT_*H_*32 + 255)/256, 256>>>(k_k, k_a);

    // 7) sequential recurrence (128 blocks x 64 threads, cp=4)
    rec_kernel<<<128, 64>>>();

    // 8) GroupNorm + bonus + gate (-> bf16 hi/lo)
    post_kernel<<<(BT_*H_*32 + 255)/256, 256>>>(r_k, gnw, gnb);

    // 9) output projection (HMMA)
    {
        HJobs hj;
        hj.j[0] = { p_preh, p_prel, p_wh + 3*C_*C_, p_wl + 3*C_*C_,
                    out, nullptr, nullptr, nullptr, C_, C_, 0 };
        hj.j[1] = hj.j[0];
        hj.j[2] = hj.j[0];
        hg3_kernel<128><<<dim3(C_/128, BT_/AROWS, 1), 512, HS3_128>>>(hj);
    }
}

// round 15
// speedup vs baseline: 1.3081x; 1.0404x over previous
#include <cuda_runtime.h>
#include <cuda_bf16.h>
#include <math.h>
#include <stdint.h>

#define B_ 2
#define T_ 2048
#define C_ 1024
#define H_ 16
#define D_ 64
#define BT_ (B_*T_)
#define RW_ 64
#define RA_ 64
#define RG_ 160
#define EPS_ 6.4e-4f   // D * 1e-5
#define RCHUNK 8
#define RROWS 16

// ---------------- packed f32x2 helpers --------------------------------------
__device__ __forceinline__ unsigned long long f32x2_fma(
    unsigned long long a, unsigned long long b, unsigned long long c) {
    unsigned long long d;
    asm("fma.rn.f32x2 %0, %1, %2, %3;" : "=l"(d) : "l"(a), "l"(b), "l"(c));
    return d;
}
__device__ __forceinline__ unsigned long long f32x2_pack(float lo, float hi) {
    unsigned long long d;
    asm("mov.b64 %0, {%1, %2};" : "=l"(d) : "f"(lo), "f"(hi));
    return d;
}
__device__ __forceinline__ float2 f32x2_unpack(unsigned long long v) {
    float lo, hi;
    asm("mov.b64 {%0, %1}, %2;" : "=f"(lo), "=f"(hi) : "l"(v));
    return make_float2(lo, hi);
}
__device__ __forceinline__ uint32_t smem_u32(const void* p) {
    uint32_t a;
    asm("{ .reg .u64 t; cvta.to.shared.u64 t, %1; cvt.u32.u64 %0, t; }"
        : "=r"(a) : "l"(p));
    return a;
}
__device__ __forceinline__ void cp16(uint32_t d, const void* s) {
    asm volatile("cp.async.cg.shared.global [%0], [%1], 16;"
                 :: "r"(d), "l"(s));
}
__device__ __forceinline__ void cp16z(uint32_t d, const void* s, bool ok) {
    int n = ok ? 16 : 0;
    asm volatile("cp.async.cg.shared.global [%0], [%1], 16, %2;"
                 :: "r"(d), "l"(s), "r"(n));
}

// ---------------- scratch (device globals: allocation-free) ----------------
__device__ __nv_bfloat16 g_xrh[BT_*C_], g_xrl[BT_*C_];
__device__ __nv_bfloat16 g_xkh[BT_*C_], g_xkl[BT_*C_];
__device__ __nv_bfloat16 g_xvh[BT_*C_], g_xvl[BT_*C_];
__device__ __nv_bfloat16 g_xwh[BT_*C_], g_xwl[BT_*C_];
__device__ __nv_bfloat16 g_xah[BT_*C_], g_xal[BT_*C_];
__device__ __nv_bfloat16 g_xgh[BT_*C_], g_xgl[BT_*C_];
__device__ __nv_bfloat16 g_preh[BT_*C_], g_prel[BT_*C_];
__device__ __nv_bfloat16 g_wh[4][C_*C_], g_wl[4][C_*C_];   // Wr,Wk,Wv,Wo
__device__ __nv_bfloat16 g_wAh[RW_*C_], g_wAl[RW_*C_];
__device__ __nv_bfloat16 g_aAh[RA_*C_], g_aAl[RA_*C_];
__device__ __nv_bfloat16 g_gAh[RG_*C_], g_gAl[RG_*C_];
__device__ __nv_bfloat16 g_wBh[C_*RW_], g_wBl[C_*RW_];
__device__ __nv_bfloat16 g_aBh[C_*RA_], g_aBl[C_*RA_];
__device__ __nv_bfloat16 g_gBh[C_*RG_], g_gBl[C_*RG_];
__device__ __nv_bfloat16 g_w1h[BT_*RW_], g_w1l[BT_*RW_];
__device__ __nv_bfloat16 g_a1h[BT_*RA_], g_a1l[BT_*RA_];
__device__ __nv_bfloat16 g_g1h[BT_*RG_], g_g1l[BT_*RG_];
__device__ float g_r [BT_*C_];
__device__ float g_k [BT_*C_];
__device__ float g_v [BT_*C_];
__device__ float g_decay[BT_*C_];
__device__ float g_a [BT_*C_];
__device__ float g_g [BT_*C_];
__device__ float g_ain[BT_*C_];
__device__ float g_bin[BT_*C_];
__device__ float g_o [BT_*C_];
__device__ float g_w0[C_];

// ---------------- fp32 -> bf16 hi/lo split helpers --------------------------
__device__ __forceinline__ void split4(float4 m, uint2& hi, uint2& lo) {
    __nv_bfloat16 h0 = __float2bfloat16_rn(m.x);
    __nv_bfloat16 h1 = __float2bfloat16_rn(m.y);
    __nv_bfloat16 h2 = __float2bfloat16_rn(m.z);
    __nv_bfloat16 h3 = __float2bfloat16_rn(m.w);
    __nv_bfloat16 l0 = __float2bfloat16_rn(m.x - __bfloat162float(h0));
    __nv_bfloat16 l1 = __float2bfloat16_rn(m.y - __bfloat162float(h1));
    __nv_bfloat16 l2 = __float2bfloat16_rn(m.z - __bfloat162float(h2));
    __nv_bfloat16 l3 = __float2bfloat16_rn(m.w - __bfloat162float(h3));
    __nv_bfloat162 ph0 = __halves2bfloat162(h0, h1);
    __nv_bfloat162 ph1 = __halves2bfloat162(h2, h3);
    __nv_bfloat162 pl0 = __halves2bfloat162(l0, l1);
    __nv_bfloat162 pl1 = __halves2bfloat162(l2, l3);
    hi.x = *reinterpret_cast<uint32_t*>(&ph0);
    hi.y = *reinterpret_cast<uint32_t*>(&ph1);
    lo.x = *reinterpret_cast<uint32_t*>(&pl0);
    lo.y = *reinterpret_cast<uint32_t*>(&pl1);
}
__device__ __forceinline__ uint32_t pack_bf2(float a, float b, uint32_t& lov) {
    __nv_bfloat16 h0 = __float2bfloat16_rn(a), h1 = __float2bfloat16_rn(b);
    __nv_bfloat16 l0 = __float2bfloat16_rn(a - __bfloat162float(h0));
    __nv_bfloat16 l1 = __float2bfloat16_rn(b - __bfloat162float(h1));
    __nv_bfloat162 hh = __halves2bfloat162(h0, h1);
    __nv_bfloat162 ll = __halves2bfloat162(l0, l1);
    lov = *reinterpret_cast<uint32_t*>(&ll);
    return *reinterpret_cast<uint32_t*>(&hh);
}

// ---------------- weight conversion: fp32 -> bf16 hi/lo ---------------------
struct WcJob { const float* src; __nv_bfloat16 *h, *l; int n; };
struct WcJobs { WcJob j[10]; };
__global__ void wconv_kernel(WcJobs jobs)
{
    WcJob jb = jobs.j[blockIdx.y];
    int i = (blockIdx.x * blockDim.x + threadIdx.x) * 4;
    if (i >= jb.n) return;
    float4 v = *(const float4*)(jb.src + i);
    uint2 hi, lo;
    split4(v, hi, lo);
    *(uint2*)(jb.h + i) = hi;
    *(uint2*)(jb.l + i) = lo;
}

// ---------------- token-shift mixing: all 6 emitted as bf16 hi/lo -----------
__global__ void mix_kernel(const float* __restrict__ x,
    const float* __restrict__ cr, const float* __restrict__ cw,
    const float* __restrict__ ck, const float* __restrict__ cv,
    const float* __restrict__ ca, const float* __restrict__ cg)
{
    int i = blockIdx.x * blockDim.x + threadIdx.x;
    if (i >= BT_*C_/4) return;
    int idx = i * 4;
    int c  = idx & (C_-1);
    int bt = idx >> 10;
    int t  = bt & (T_-1);
    float4 xv = *(const float4*)(x + idx);
    float4 xs = make_float4(0.f,0.f,0.f,0.f);
    if (t) xs = *(const float4*)(x + idx - C_);
    float4 d = make_float4(xs.x-xv.x, xs.y-xv.y, xs.z-xv.z, xs.w-xv.w);
    float4 m; uint2 hi, lo;
#define MIXS(cf, ah, al) { float4 cc = *(const float4*)((cf)+c); \
    m = make_float4(xv.x + d.x*cc.x, xv.y + d.y*cc.y, \
                    xv.z + d.z*cc.z, xv.w + d.w*cc.w); \
    split4(m, hi, lo); \
    *(uint2*)((ah) + idx) = hi; *(uint2*)((al) + idx) = lo; }
    MIXS(cr, g_xrh, g_xrl)
    MIXS(ck, g_xkh, g_xkl)
    MIXS(cv, g_xvh, g_xvl)
    MIXS(cw, g_xwh, g_xwl)
    MIXS(ca, g_xah, g_xal)
    MIXS(cg, g_xgh, g_xgl)
#undef MIXS
}

// ---------------- w0 = base + cumsum(softplus(delta)) ----------------------
__global__ void w0_kernel(const float* __restrict__ base,
                          const float* __restrict__ delta)
{
    __shared__ float s[C_];
    int tid = threadIdx.x;
    float v = 0.f;
    if (tid > 0) {
        float d = delta[tid-1];
        v = (d > 20.f) ? d : log1pf(expf(d));
    }
    s[tid] = v;
    __syncthreads();
    for (int off = 1; off < C_; off <<= 1) {
        float t = (tid >= off) ? s[tid-off] : 0.f;
        __syncthreads();
        s[tid] += t;
        __syncthreads();
    }
    g_w0[tid] = base[0] + s[tid];
}

// ================ generic HMMA bf16-split GEMM (512 thr, 3-stage async) =====
// Up to 6 jobs per launch via blockIdx.z (merges independent GEMMs into
// one grid so small jobs pack into the big jobs' tail waves).
struct HJob { const __nv_bfloat16 *Ah, *Al, *Bh, *Bl;
              float* Cf; __nv_bfloat16 *Ch, *Cl;
              const float* bias; int N, K, act; };
struct HJobs { HJob j[6]; };

#define LDK 40
#define AROWS 256
#define ASZ2 (AROWS*LDK)

__device__ __forceinline__ void ldm_x4(uint32_t addr, uint32_t r[4]) {
    asm volatile("ldmatrix.sync.aligned.m8n8.x4.shared.b16 {%0,%1,%2,%3}, [%4];"
        : "=r"(r[0]), "=r"(r[1]), "=r"(r[2]), "=r"(r[3]) : "r"(addr));
}
__device__ __forceinline__ void ldm_x2(uint32_t addr, uint32_t r[2]) {
    asm volatile("ldmatrix.sync.aligned.m8n8.x2.shared.b16 {%0,%1}, [%2];"
        : "=r"(r[0]), "=r"(r[1]) : "r"(addr));
}
__device__ __forceinline__ void mma_bf16(float* d, const uint32_t* a,
                                         const uint32_t* b) {
    asm volatile("mma.sync.aligned.m16n8k16.row.col.f32.bf16.bf16.f32 "
        "{%0,%1,%2,%3}, {%4,%5,%6,%7}, {%8,%9}, {%0,%1,%2,%3};"
        : "+f"(d[0]), "+f"(d[1]), "+f"(d[2]), "+f"(d[3])
        : "r"(a[0]), "r"(a[1]), "r"(a[2]), "r"(a[3]), "r"(b[0]), "r"(b[1]));
}

__device__ __forceinline__ void emit2(const HJob& jb, int row, int col,
                                      float v0, float v1)
{
    size_t idx = (size_t)row * jb.N + col;
    int act = jb.act;
    if (act == 0) {
        *(float2*)(jb.Cf + idx) = make_float2(v0, v1);
    } else if (act == 3) {
        float t0 = g_w0[col]   + v0 + jb.bias[col];
        float t1 = g_w0[col+1] + v1 + jb.bias[col+1];
        float n0 = -t0, n1 = -t1;
        float s0 = (n0 > 20.f) ? n0 : log1pf(expf(n0));
        float s1 = (n1 > 20.f) ? n1 : log1pf(expf(n1));
        *(float2*)(jb.Cf + idx) =
            make_float2(expf(-expf(-s0 - 0.5f)), expf(-expf(-s1 - 0.5f)));
    } else if (act == 5) {
        float y0 = 1.f / (1.f + expf(-(v0 + jb.bias[col])));
        float y1 = 1.f / (1.f + expf(-(v1 + jb.bias[col+1])));
        *(float2*)(jb.Cf + idx) = make_float2(y0, y1);
    } else {
        if (act == 1) { v0 = tanhf(v0); v1 = tanhf(v1); }
        else if (act == 2) {
            v0 = 1.f / (1.f + expf(-v0));
            v1 = 1.f / (1.f + expf(-v1));
        }
        uint32_t lov;
        uint32_t hiv = pack_bf2(v0, v1, lov);
        *(uint32_t*)(jb.Ch + idx) = hiv;
        *(uint32_t*)(jb.Cl + idx) = lov;
    }
}

__global__ void __launch_bounds__(512, 1) hg3_kernel(HJobs jobs)
{
    HJob jb = jobs.j[blockIdx.z];
    const int N = jb.N, K = jb.K;
    const int m0 = blockIdx.y * AROWS;
    const int n0 = blockIdx.x * 128;
    if (n0 >= N) return;

    constexpr int BSZ  = 128 * LDK;
    constexpr int STGE = 2*ASZ2 + 2*BSZ;
    constexpr int MTt  = 4;

    extern __shared__ __nv_bfloat16 sm3[];
    uint32_t s0 = smem_u32(sm3);

    int tid  = threadIdx.x;
    int wid  = tid >> 5;
    int lane = tid & 31;
    int wm = (wid & 3) * 64;
    int wn = (wid >> 2) * 32;

    int alr = tid >> 1, alseg = tid & 1;
    const __nv_bfloat16* sAh = jb.Ah + (size_t)(m0 + alr) * K + alseg * 16;
    const __nv_bfloat16* sAl = jb.Al + (size_t)(m0 + alr) * K + alseg * 16;
    uint32_t aoff = (alr * LDK + alseg * 16) * 2;

    int brow = (tid >> 1) & 127, bseg = tid & 1;
    bool bok = (tid < 256) && ((n0 + brow) < N);
    const __nv_bfloat16* sBh = jb.Bh + (size_t)(n0 + brow) * K + bseg * 16;
    const __nv_bfloat16* sBl = jb.Bl + (size_t)(n0 + brow) * K + bseg * 16;
    uint32_t boff = (2*ASZ2 + brow * LDK + bseg * 16) * 2;
    bool bthr = tid < 256;

    float acc[MTt][4][4];
#pragma unroll
    for (int i = 0; i < MTt; i++)
#pragma unroll
        for (int j = 0; j < 4; j++)
#pragma unroll
            for (int q = 0; q < 4; q++) acc[i][j][q] = 0.f;

    uint32_t rowA = (lane & 15) * (LDK*2);
    uint32_t colA = (lane >> 4) * 16;
    uint32_t rowB = (lane & 7)  * (LDK*2);
    uint32_t colB = ((lane >> 3) & 1) * 16;

    const int ncit = K >> 5;

#define HG3_ISSUE(c, st) do { \
        uint32_t dbase = s0 + (uint32_t)(st) * (STGE*2); \
        int adv = (c) * 32; \
        cp16(dbase + aoff,               sAh + adv); \
        cp16(dbase + aoff + 16,          sAh + adv + 8); \
        cp16(dbase + ASZ2*2 + aoff,      sAl + adv); \
        cp16(dbase + ASZ2*2 + aoff + 16, sAl + adv + 8); \
        if (bthr) { \
            cp16z(dbase + boff,               sBh + adv,     bok); \
            cp16z(dbase + boff + 16,          sBh + adv + 8, bok); \
            cp16z(dbase + BSZ*2 + boff,       sBl + adv,     bok); \
            cp16z(dbase + BSZ*2 + boff + 16,  sBl + adv + 8, bok); \
        } \
        asm volatile("cp.async.commit_group;"); \
    } while (0)

    HG3_ISSUE(0, 0);
    if (ncit > 1) HG3_ISSUE(1, 1);

    int st = 0;
    for (int c = 0; c < ncit; c++) {
        if (c + 1 < ncit)
            asm volatile("cp.async.wait_group 1;");
        else
            asm volatile("cp.async.wait_group 0;");
        __syncthreads();

        if (c + 2 < ncit) {
            int st2 = st + 2; if (st2 >= 3) st2 -= 3;
            HG3_ISSUE(c + 2, st2);
        }

        uint32_t sb    = s0 + (uint32_t)st * (STGE*2);
        uint32_t sAh_b = sb;
        uint32_t sAl_b = sb + ASZ2*2;
        uint32_t sBh_b = sb + 2*ASZ2*2;
        uint32_t sBl_b = sb + (2*ASZ2 + BSZ)*2;

#pragma unroll
        for (int ks = 0; ks < 2; ks++) {
            uint32_t bfh[4][2], bfl[4][2];
#pragma unroll
            for (int nt = 0; nt < 4; nt++) {
                uint32_t bo = (wn + nt*8) * (LDK*2) + rowB + ks*32 + colB;
                ldm_x2(sBh_b + bo, bfh[nt]);
                ldm_x2(sBl_b + bo, bfl[nt]);
            }
#pragma unroll
            for (int mt = 0; mt < MTt; mt++) {
                uint32_t afh[4], afl[4];
                uint32_t ao = (wm + mt*16) * (LDK*2) + rowA + ks*32 + colA;
                ldm_x4(sAh_b + ao, afh);
                ldm_x4(sAl_b + ao, afl);
#pragma unroll
                for (int nt = 0; nt < 4; nt++) {
                    mma_bf16(acc[mt][nt], afh, bfh[nt]);
                    mma_bf16(acc[mt][nt], afh, bfl[nt]);
                    mma_bf16(acc[mt][nt], afl, bfh[nt]);
                }
            }
        }
        if (++st == 3) st = 0;
    }
#undef HG3_ISSUE

    int g = lane >> 2, tg = lane & 3;
#pragma unroll
    for (int mt = 0; mt < MTt; mt++) {
#pragma unroll
        for (int nt = 0; nt < 4; nt++) {
            int cb = n0 + wn + nt*8 + 2*tg;
            if (cb >= N) continue;      // general N guard (small-N jobs)
            int r0 = m0 + wm + mt*16 + g;
            emit2(jb, r0,     cb, acc[mt][nt][0], acc[mt][nt][1]);
            emit2(jb, r0 + 8, cb, acc[mt][nt][2], acc[mt][nt][3]);
        }
    }
}

#define HS3_128 ((2*ASZ2 + 2*128*LDK) * 2 * 3)

// ---------------- kk normalize / a_in / b_in / k update --------------------
__global__ void kk_kernel(const float* __restrict__ kkc,
                          const float* __restrict__ kac)
{
    int gid  = blockIdx.x * blockDim.x + threadIdx.x;
    int lane = gid & 31;
    int grp  = gid >> 5;
    if (grp >= BT_*H_) return;
    int bt = grp / H_, h = grp % H_;
    int base = bt * C_ + h * D_;
    int c0   = h * D_;

    float k0v = g_k[base + lane],      k1v = g_k[base + 32 + lane];
    float a0  = g_a[base + lane],      a1  = g_a[base + 32 + lane];
    float kk0 = k0v * kkc[c0 + lane],  kk1 = k1v * kkc[c0 + 32 + lane];

    float ss = kk0*kk0 + kk1*kk1;
#pragma unroll
    for (int o = 16; o; o >>= 1) ss += __shfl_xor_sync(0xffffffffu, ss, o);
    float inv = 1.f / fmaxf(sqrtf(ss), 1e-12f);
    kk0 *= inv; kk1 *= inv;

    g_ain[base + lane]      = -kk0;
    g_ain[base + 32 + lane] = -kk1;
    g_bin[base + lane]      = kk0 * a0;
    g_bin[base + 32 + lane] = kk1 * a1;
    g_k[base + lane]        = k0v * (1.f + (a0 - 1.f) * kac[c0 + lane]);
    g_k[base + 32 + lane]   = k1v * (1.f + (a1 - 1.f) * kac[c0 + 32 + lane]);
}

// ---------------- RWKV-7 recurrence (v4: row-split, 128 blocks x 128 thr) ---
__global__ void __launch_bounds__(128, 1) rec_kernel()
{
    int blk = blockIdx.x;
    int bh  = blk >> 2;
    int rb  = blk & 3;
    int b = bh >> 4, h = bh & 15;
    size_t base = (size_t)b * T_ * C_ + h * D_;

    __shared__ alignas(16) float rsm[2][6][RCHUNK][64];

    int tid = threadIdx.x;
    int row = rb * RROWS + (tid >> 3);
    int cp  = tid & 7;
    int c0  = cp * 8;

    const float* srcs[6] = { g_r, g_decay, g_k, g_v, g_ain, g_bin };
    const float* gp[6];
    uint32_t sp_[6];
#pragma unroll
    for (int it = 0; it < 6; it++) {
        int f  = tid + it * 128;
        int q  = f & 15;
        int st = (f >> 4) & (RCHUNK-1);
        int vc = f >> 7;
        gp[it]  = srcs[vc] + base + (size_t)st * C_ + q * 4;
        sp_[it] = (uint32_t)((vc * RCHUNK + st) * 64 + q * 4);
    }

    unsigned long long S[4] = {0ull, 0ull, 0ull, 0ull};

    float4 pf[6];
#pragma unroll
    for (int it = 0; it < 6; it++) pf[it] = *(const float4*)gp[it];

    float* smbase = &rsm[0][0][0][0];
    const int NCH = T_ / RCHUNK;
    for (int ch = 0; ch < NCH; ch++) {
        float* buf = smbase + (ch & 1) * (6*RCHUNK*64);
#pragma unroll
        for (int it = 0; it < 6; it++)
            *(float4*)(buf + sp_[it]) = pf[it];
        __syncthreads();
        if (ch + 1 < NCH) {
            size_t adv = (size_t)(ch + 1) * RCHUNK * C_;
#pragma unroll
            for (int it = 0; it < 6; it++)
                pf[it] = *(const float4*)(gp[it] + adv);
        }

        size_t obase = base + (size_t)ch * RCHUNK * C_ + row;
#pragma unroll 2
        for (int s = 0; s < RCHUNK; s++) {
            const float* rv = buf + (0*RCHUNK + s) * 64;
            const float* wv = buf + (1*RCHUNK + s) * 64;
            const float* kv = buf + (2*RCHUNK + s) * 64;
            const float* vv = buf + (3*RCHUNK + s) * 64;
            const float* av = buf + (4*RCHUNK + s) * 64;
            const float* bv = buf + (5*RCHUNK + s) * 64;

            ulonglong2 aA = *(const ulonglong2*)(av + c0);
            ulonglong2 aB = *(const ulonglong2*)(av + c0 + 4);
            unsigned long long sacc = f32x2_fma(S[0], aA.x, 0ull);
            sacc = f32x2_fma(S[1], aA.y, sacc);
            sacc = f32x2_fma(S[2], aB.x, sacc);
            sacc = f32x2_fma(S[3], aB.y, sacc);
            float2 spp = f32x2_unpack(sacc);
            float sa = spp.x + spp.y;
            sa += __shfl_xor_sync(0xffffffffu, sa, 1);
            sa += __shfl_xor_sync(0xffffffffu, sa, 2);
            sa += __shfl_xor_sync(0xffffffffu, sa, 4);

            float vj = vv[row];
            ulonglong2 wA = *(const ulonglong2*)(wv + c0);
            ulonglong2 wB = *(const ulonglong2*)(wv + c0 + 4);
            ulonglong2 bA = *(const ulonglong2*)(bv + c0);
            ulonglong2 bB = *(const ulonglong2*)(bv + c0 + 4);
            ulonglong2 kA = *(const ulonglong2*)(kv + c0);
            ulonglong2 kB = *(const ulonglong2*)(kv + c0 + 4);
            ulonglong2 rA = *(const ulonglong2*)(rv + c0);
            ulonglong2 rB = *(const ulonglong2*)(rv + c0 + 4);

            unsigned long long sa2 = f32x2_pack(sa, sa);
            unsigned long long v2  = f32x2_pack(vj, vj);

            S[0] = f32x2_fma(v2, kA.x, f32x2_fma(sa2, bA.x, f32x2_fma(S[0], wA.x, 0ull)));
            S[1] = f32x2_fma(v2, kA.y, f32x2_fma(sa2, bA.y, f32x2_fma(S[1], wA.y, 0ull)));
            S[2] = f32x2_fma(v2, kB.x, f32x2_fma(sa2, bB.x, f32x2_fma(S[2], wB.x, 0ull)));
            S[3] = f32x2_fma(v2, kB.y, f32x2_fma(sa2, bB.y, f32x2_fma(S[3], wB.y, 0ull)));

            unsigned long long oacc = f32x2_fma(S[0], rA.x, 0ull);
            oacc = f32x2_fma(S[1], rA.y, oacc);
            oacc = f32x2_fma(S[2], rB.x, oacc);
            oacc = f32x2_fma(S[3], rB.y, oacc);
            float2 op = f32x2_unpack(oacc);
            float o = op.x + op.y;
            o += __shfl_xor_sync(0xffffffffu, o, 1);
            o += __shfl_xor_sync(0xffffffffu, o, 2);
            o += __shfl_xor_sync(0xffffffffu, o, 4);
            if (cp == 0) g_o[obase + (size_t)s * C_] = o;
        }
    }
}

// ---------------- GroupNorm + bonus + gate (emits bf16 hi/lo) --------------
__global__ void post_kernel(const float* __restrict__ rk,
                            const float* __restrict__ gnw,
                            const float* __restrict__ gnb)
{
    int gid  = blockIdx.x * blockDim.x + threadIdx.x;
    int lane = gid & 31;
    int grp  = gid >> 5;
    if (grp >= BT_*H_) return;
    int bt = grp / H_, h = grp % H_;
    int base = bt * C_ + h * D_;
    int c0   = h * D_;

    float o0 = g_o[base + lane], o1 = g_o[base + 32 + lane];
    float su = o0 + o1;
    float sq = o0*o0 + o1*o1;
    float r0 = g_r[base + lane], r1 = g_r[base + 32 + lane];
    float k0 = g_k[base + lane], k1 = g_k[base + 32 + lane];
    float bsum = r0*k0*rk[c0 + lane] + r1*k1*rk[c0 + 32 + lane];
#pragma unroll
    for (int o = 16; o; o >>= 1) {
        su   += __shfl_xor_sync(0xffffffffu, su,   o);
        sq   += __shfl_xor_sync(0xffffffffu, sq,   o);
        bsum += __shfl_xor_sync(0xffffffffu, bsum, o);
    }
    float mu  = su / 64.f;
    float var = sq / 64.f - mu * mu;
    float inv = rsqrtf(var + EPS_);

    float v0 = g_v[base + lane], v1 = g_v[base + 32 + lane];
    float on0 = (o0 - mu) * inv * gnw[c0 + lane]      + gnb[c0 + lane];
    float on1 = (o1 - mu) * inv * gnw[c0 + 32 + lane] + gnb[c0 + 32 + lane];
    float p0 = (on0 + bsum * v0) * g_g[base + lane];
    float p1 = (on1 + bsum * v1) * g_g[base + 32 + lane];

    __nv_bfloat16 h0 = __float2bfloat16_rn(p0);
    __nv_bfloat16 h1 = __float2bfloat16_rn(p1);
    g_preh[base + lane]      = h0;
    g_preh[base + 32 + lane] = h1;
    g_prel[base + lane]      = __float2bfloat16_rn(p0 - __bfloat162float(h0));
    g_prel[base + 32 + lane] = __float2bfloat16_rn(p1 - __bfloat162float(h1));
}

// ---------------- host launcher ---------------------------------------------
extern "C" void kernel_launch(void* const* d_in, const int* in_sizes, int n_in,
                              void* d_out, int out_size)
{
    const float* x        = (const float*)d_in[0];
    const float* x_r      = (const float*)d_in[1];
    const float* x_w      = (const float*)d_in[2];
    const float* x_k      = (const float*)d_in[3];
    const float* x_v      = (const float*)d_in[4];
    const float* x_a      = (const float*)d_in[5];
    const float* x_g      = (const float*)d_in[6];
    const float* k_k      = (const float*)d_in[7];
    const float* k_a      = (const float*)d_in[8];
    const float* r_k      = (const float*)d_in[9];
    const float* Wr       = (const float*)d_in[10];
    const float* Wk       = (const float*)d_in[11];
    const float* Wv       = (const float*)d_in[12];
    const float* Wo       = (const float*)d_in[13];
    const float* wA       = (const float*)d_in[14];
    const float* wB       = (const float*)d_in[15];
    const float* wBias    = (const float*)d_in[16];
    const float* aA       = (const float*)d_in[17];
    const float* aB       = (const float*)d_in[18];
    const float* aBias    = (const float*)d_in[19];
    const float* gA       = (const float*)d_in[20];
    const float* gB       = (const float*)d_in[21];
    const float* gnw      = (const float*)d_in[22];
    const float* gnb      = (const float*)d_in[23];
    const float* w0_base  = (const float*)d_in[24];
    const float* w0_delta = (const float*)d_in[25];
    float* out = (float*)d_out;

#define SYM(p, s) cudaGetSymbolAddress((void**)&p, s)
    float *p_r,*p_k,*p_v,*p_dec,*p_a,*p_g;
    __nv_bfloat16 *p_xrh,*p_xrl,*p_xkh,*p_xkl,*p_xvh,*p_xvl;
    __nv_bfloat16 *p_xwh,*p_xwl,*p_xah,*p_xal,*p_xgh,*p_xgl;
    __nv_bfloat16 *p_preh,*p_prel,*p_wh,*p_wl;
    __nv_bfloat16 *p_wAh,*p_wAl,*p_aAh,*p_aAl,*p_gAh,*p_gAl;
    __nv_bfloat16 *p_wBh,*p_wBl,*p_aBh,*p_aBl,*p_gBh,*p_gBl;
    __nv_bfloat16 *p_w1h,*p_w1l,*p_a1h,*p_a1l,*p_g1h,*p_g1l;
    SYM(p_r, g_r); SYM(p_k, g_k); SYM(p_v, g_v);
    SYM(p_dec, g_decay); SYM(p_a, g_a); SYM(p_g, g_g);
    SYM(p_xrh, g_xrh); SYM(p_xrl, g_xrl);
    SYM(p_xkh, g_xkh); SYM(p_xkl, g_xkl);
    SYM(p_xvh, g_xvh); SYM(p_xvl, g_xvl);
    SYM(p_xwh, g_xwh); SYM(p_xwl, g_xwl);
    SYM(p_xah, g_xah); SYM(p_xal, g_xal);
    SYM(p_xgh, g_xgh); SYM(p_xgl, g_xgl);
    SYM(p_preh, g_preh); SYM(p_prel, g_prel);
    SYM(p_wh, g_wh); SYM(p_wl, g_wl);
    SYM(p_wAh, g_wAh); SYM(p_wAl, g_wAl);
    SYM(p_aAh, g_aAh); SYM(p_aAl, g_aAl);
    SYM(p_gAh, g_gAh); SYM(p_gAl, g_gAl);
    SYM(p_wBh, g_wBh); SYM(p_wBl, g_wBl);
    SYM(p_aBh, g_aBh); SYM(p_aBl, g_aBl);
    SYM(p_gBh, g_gBh); SYM(p_gBl, g_gBl);
    SYM(p_w1h, g_w1h); SYM(p_w1l, g_w1l);
    SYM(p_a1h, g_a1h); SYM(p_a1l, g_a1l);
    SYM(p_g1h, g_g1h); SYM(p_g1l, g_g1l);
#undef SYM

    cudaFuncSetAttribute(hg3_kernel,
        cudaFuncAttributeMaxDynamicSharedMemorySize, HS3_128);

    // 0) all weights fp32 -> bf16 hi/lo
    {
        WcJobs wj;
        wj.j[0] = { Wr, p_wh + 0*C_*C_, p_wl + 0*C_*C_, C_*C_ };
        wj.j[1] = { Wk, p_wh + 1*C_*C_, p_wl + 1*C_*C_, C_*C_ };
        wj.j[2] = { Wv, p_wh + 2*C_*C_, p_wl + 2*C_*C_, C_*C_ };
        wj.j[3] = { Wo, p_wh + 3*C_*C_, p_wl + 3*C_*C_, C_*C_ };
        wj.j[4] = { wA, p_wAh, p_wAl, RW_*C_ };
        wj.j[5] = { aA, p_aAh, p_aAl, RA_*C_ };
        wj.j[6] = { gA, p_gAh, p_gAl, RG_*C_ };
        wj.j[7] = { wB, p_wBh, p_wBl, C_*RW_ };
        wj.j[8] = { aB, p_aBh, p_aBl, C_*RA_ };
        wj.j[9] = { gB, p_gBh, p_gBl, C_*RG_ };
        wconv_kernel<<<dim3(C_*C_/4/256, 10), 256>>>(wj);
    }

    // 1) token-shift mixes -> bf16 hi/lo (all six)
    mix_kernel<<<(BT_*C_/4 + 255)/256, 256>>>(x, x_r, x_w, x_k, x_v, x_a, x_g);

    // 2) w0 scan
    w0_kernel<<<1, C_>>>(w0_base, w0_delta);

    // 3) r/k/v projections + LoRA stage 1, ONE launch (6 jobs).
    //    Stage-1 jobs have N<=160: only block-col 0..1 do work; the rest
    //    exit at n0>=N, so they pack into rkv's tail wave.
    {
        HJobs hj;
        hj.j[0] = { p_xrh, p_xrl, p_wh + 0*C_*C_, p_wl + 0*C_*C_,
                    p_r, nullptr, nullptr, nullptr, C_, C_, 0 };
        hj.j[1] = { p_xkh, p_xkl, p_wh + 1*C_*C_, p_wl + 1*C_*C_,
                    p_k, nullptr, nullptr, nullptr, C_, C_, 0 };
        hj.j[2] = { p_xvh, p_xvl, p_wh + 2*C_*C_, p_wl + 2*C_*C_,
                    p_v, nullptr, nullptr, nullptr, C_, C_, 0 };
        hj.j[3] = { p_xwh, p_xwl, p_wAh, p_wAl,
                    nullptr, p_w1h, p_w1l, nullptr, RW_, C_, 1 };   // tanh
        hj.j[4] = { p_xah, p_xal, p_aAh, p_aAl,
                    nullptr, p_a1h, p_a1l, nullptr, RA_, C_, 6 };   // none
        hj.j[5] = { p_xgh, p_xgl, p_gAh, p_gAl,
                    nullptr, p_g1h, p_g1l, nullptr, RG_, C_, 2 };   // sigmoid
        hg3_kernel<<<dim3(C_/128, BT_/AROWS, 6), 512, HS3_128>>>(hj);
    }

    // 4) LoRA stage 2 (3 jobs, fused epilogues)
    {
        HJobs hj;
        hj.j[0] = { p_w1h, p_w1l, p_wBh, p_wBl,
                    p_dec, nullptr, nullptr, wBias, C_, RW_, 3 };   // decay
        hj.j[1] = { p_a1h, p_a1l, p_aBh, p_aBl,
                    p_a, nullptr, nullptr, aBias, C_, RA_, 5 };     // sigm+bias
        hj.j[2] = { p_g1h, p_g1l, p_gBh, p_gBl,
                    p_g, nullptr, nullptr, nullptr, C_, RG_, 0 };
        hj.j[3] = hj.j[0]; hj.j[4] = hj.j[0]; hj.j[5] = hj.j[0];
        hg3_kernel<<<dim3(C_/128, BT_/AROWS, 3), 512, HS3_128>>>(hj);
    }

    // 5) kk normalize / a_in / b_in / k update
    kk_kernel<<<(BT_*H_*32 + 255)/256, 256>>>(k_k, k_a);

    // 6) sequential recurrence (v4: 128 blocks x 128 threads)
    rec_kernel<<<128, 128>>>();

    // 7) GroupNorm + bonus + gate (-> bf16 hi/lo)
    post_kernel<<<(BT_*H_*32 + 255)/256, 256>>>(r_k, gnw, gnb);

    // 8) output projection
    {
        HJobs hj;
        hj.j[0] = { p_preh, p_prel, p_wh + 3*C_*C_, p_wl + 3*C_*C_,
                    out, nullptr, nullptr, nullptr, C_, C_, 0 };
        hj.j[1] = hj.j[0]; hj.j[2] = hj.j[0];
        hj.j[3] = hj.j[0]; hj.j[4] = hj.j[0]; hj.j[5] = hj.j[0];
        hg3_kernel<<<dim3(C_/128, BT_/AROWS, 1), 512, HS3_128>>>(hj);
    }
}

// round 16
// speedup vs baseline: 1.3351x; 1.0206x over previous
#include <cuda_runtime.h>
#include <cuda_bf16.h>
#include <math.h>
#include <stdint.h>

#define B_ 2
#define T_ 2048
#define C_ 1024
#define H_ 16
#define D_ 64
#define BT_ (B_*T_)
#define RW_ 64
#define RA_ 64
#define RG_ 160
#define EPS_ 6.4e-4f   // D * 1e-5
#define RCHUNK 16
#define RROWS 16

// ---------------- packed f32x2 helpers --------------------------------------
__device__ __forceinline__ unsigned long long f32x2_fma(
    unsigned long long a, unsigned long long b, unsigned long long c) {
    unsigned long long d;
    asm("fma.rn.f32x2 %0, %1, %2, %3;" : "=l"(d) : "l"(a), "l"(b), "l"(c));
    return d;
}
__device__ __forceinline__ unsigned long long f32x2_pack(float lo, float hi) {
    unsigned long long d;
    asm("mov.b64 %0, {%1, %2};" : "=l"(d) : "f"(lo), "f"(hi));
    return d;
}
__device__ __forceinline__ float2 f32x2_unpack(unsigned long long v) {
    float lo, hi;
    asm("mov.b64 {%0, %1}, %2;" : "=f"(lo), "=f"(hi) : "l"(v));
    return make_float2(lo, hi);
}
__device__ __forceinline__ uint32_t smem_u32(const void* p) {
    uint32_t a;
    asm("{ .reg .u64 t; cvta.to.shared.u64 t, %1; cvt.u32.u64 %0, t; }"
        : "=r"(a) : "l"(p));
    return a;
}
__device__ __forceinline__ void cp16(uint32_t d, const void* s) {
    asm volatile("cp.async.cg.shared.global [%0], [%1], 16;"
                 :: "r"(d), "l"(s));
}
__device__ __forceinline__ void cp16z(uint32_t d, const void* s, bool ok) {
    int n = ok ? 16 : 0;
    asm volatile("cp.async.cg.shared.global [%0], [%1], 16, %2;"
                 :: "r"(d), "l"(s), "r"(n));
}

// ---------------- scratch (device globals: allocation-free) ----------------
__device__ __nv_bfloat16 g_xrh[BT_*C_], g_xrl[BT_*C_];
__device__ __nv_bfloat16 g_xkh[BT_*C_], g_xkl[BT_*C_];
__device__ __nv_bfloat16 g_xvh[BT_*C_], g_xvl[BT_*C_];
__device__ __nv_bfloat16 g_xwh[BT_*C_], g_xwl[BT_*C_];
__device__ __nv_bfloat16 g_xah[BT_*C_], g_xal[BT_*C_];
__device__ __nv_bfloat16 g_xgh[BT_*C_], g_xgl[BT_*C_];
__device__ __nv_bfloat16 g_preh[BT_*C_], g_prel[BT_*C_];
__device__ __nv_bfloat16 g_wh[4][C_*C_], g_wl[4][C_*C_];   // Wr,Wk,Wv,Wo
__device__ __nv_bfloat16 g_wAh[RW_*C_], g_wAl[RW_*C_];
__device__ __nv_bfloat16 g_aAh[RA_*C_], g_aAl[RA_*C_];
__device__ __nv_bfloat16 g_gAh[RG_*C_], g_gAl[RG_*C_];
__device__ __nv_bfloat16 g_wBh[C_*RW_], g_wBl[C_*RW_];
__device__ __nv_bfloat16 g_aBh[C_*RA_], g_aBl[C_*RA_];
__device__ __nv_bfloat16 g_gBh[C_*RG_], g_gBl[C_*RG_];
__device__ __nv_bfloat16 g_w1h[BT_*RW_], g_w1l[BT_*RW_];
__device__ __nv_bfloat16 g_a1h[BT_*RA_], g_a1l[BT_*RA_];
__device__ __nv_bfloat16 g_g1h[BT_*RG_], g_g1l[BT_*RG_];
__device__ float g_r [BT_*C_];
__device__ float g_k [BT_*C_];
__device__ float g_v [BT_*C_];
__device__ float g_decay[BT_*C_];
__device__ float g_a [BT_*C_];
__device__ float g_g [BT_*C_];
__device__ float g_ain[BT_*C_];
__device__ float g_bin[BT_*C_];
__device__ float g_o [BT_*C_];
__device__ float g_w0[C_];

// ---------------- fp32 -> bf16 hi/lo split helpers --------------------------
__device__ __forceinline__ void split4(float4 m, uint2& hi, uint2& lo) {
    __nv_bfloat16 h0 = __float2bfloat16_rn(m.x);
    __nv_bfloat16 h1 = __float2bfloat16_rn(m.y);
    __nv_bfloat16 h2 = __float2bfloat16_rn(m.z);
    __nv_bfloat16 h3 = __float2bfloat16_rn(m.w);
    __nv_bfloat16 l0 = __float2bfloat16_rn(m.x - __bfloat162float(h0));
    __nv_bfloat16 l1 = __float2bfloat16_rn(m.y - __bfloat162float(h1));
    __nv_bfloat16 l2 = __float2bfloat16_rn(m.z - __bfloat162float(h2));
    __nv_bfloat16 l3 = __float2bfloat16_rn(m.w - __bfloat162float(h3));
    __nv_bfloat162 ph0 = __halves2bfloat162(h0, h1);
    __nv_bfloat162 ph1 = __halves2bfloat162(h2, h3);
    __nv_bfloat162 pl0 = __halves2bfloat162(l0, l1);
    __nv_bfloat162 pl1 = __halves2bfloat162(l2, l3);
    hi.x = *reinterpret_cast<uint32_t*>(&ph0);
    hi.y = *reinterpret_cast<uint32_t*>(&ph1);
    lo.x = *reinterpret_cast<uint32_t*>(&pl0);
    lo.y = *reinterpret_cast<uint32_t*>(&pl1);
}
__device__ __forceinline__ uint32_t pack_bf2(float a, float b, uint32_t& lov) {
    __nv_bfloat16 h0 = __float2bfloat16_rn(a), h1 = __float2bfloat16_rn(b);
    __nv_bfloat16 l0 = __float2bfloat16_rn(a - __bfloat162float(h0));
    __nv_bfloat16 l1 = __float2bfloat16_rn(b - __bfloat162float(h1));
    __nv_bfloat162 hh = __halves2bfloat162(h0, h1);
    __nv_bfloat162 ll = __halves2bfloat162(l0, l1);
    lov = *reinterpret_cast<uint32_t*>(&ll);
    return *reinterpret_cast<uint32_t*>(&hh);
}

// ---------------- weight conversion: fp32 -> bf16 hi/lo ---------------------
struct WcJob { const float* src; __nv_bfloat16 *h, *l; int n; };
struct WcJobs { WcJob j[10]; };
__global__ void wconv_kernel(WcJobs jobs)
{
    WcJob jb = jobs.j[blockIdx.y];
    int i = (blockIdx.x * blockDim.x + threadIdx.x) * 4;
    if (i >= jb.n) return;
    float4 v = *(const float4*)(jb.src + i);
    uint2 hi, lo;
    split4(v, hi, lo);
    *(uint2*)(jb.h + i) = hi;
    *(uint2*)(jb.l + i) = lo;
}

// ---------------- token-shift mixing: all 6 emitted as bf16 hi/lo -----------
__global__ void mix_kernel(const float* __restrict__ x,
    const float* __restrict__ cr, const float* __restrict__ cw,
    const float* __restrict__ ck, const float* __restrict__ cv,
    const float* __restrict__ ca, const float* __restrict__ cg)
{
    int i = blockIdx.x * blockDim.x + threadIdx.x;
    if (i >= BT_*C_/4) return;
    int idx = i * 4;
    int c  = idx & (C_-1);
    int bt = idx >> 10;
    int t  = bt & (T_-1);
    float4 xv = *(const float4*)(x + idx);
    float4 xs = make_float4(0.f,0.f,0.f,0.f);
    if (t) xs = *(const float4*)(x + idx - C_);
    float4 d = make_float4(xs.x-xv.x, xs.y-xv.y, xs.z-xv.z, xs.w-xv.w);
    float4 m; uint2 hi, lo;
#define MIXS(cf, ah, al) { float4 cc = *(const float4*)((cf)+c); \
    m = make_float4(xv.x + d.x*cc.x, xv.y + d.y*cc.y, \
                    xv.z + d.z*cc.z, xv.w + d.w*cc.w); \
    split4(m, hi, lo); \
    *(uint2*)((ah) + idx) = hi; *(uint2*)((al) + idx) = lo; }
    MIXS(cr, g_xrh, g_xrl)
    MIXS(ck, g_xkh, g_xkl)
    MIXS(cv, g_xvh, g_xvl)
    MIXS(cw, g_xwh, g_xwl)
    MIXS(ca, g_xah, g_xal)
    MIXS(cg, g_xgh, g_xgl)
#undef MIXS
}

// ---------------- w0 = base + cumsum(softplus(delta)) ----------------------
__global__ void w0_kernel(const float* __restrict__ base,
                          const float* __restrict__ delta)
{
    __shared__ float s[C_];
    int tid = threadIdx.x;
    float v = 0.f;
    if (tid > 0) {
        float d = delta[tid-1];
        v = (d > 20.f) ? d : log1pf(expf(d));
    }
    s[tid] = v;
    __syncthreads();
    for (int off = 1; off < C_; off <<= 1) {
        float t = (tid >= off) ? s[tid-off] : 0.f;
        __syncthreads();
        s[tid] += t;
        __syncthreads();
    }
    g_w0[tid] = base[0] + s[tid];
}

// ================ generic HMMA bf16-split GEMM (512 thr, 3-stage async) =====
struct HJob { const __nv_bfloat16 *Ah, *Al, *Bh, *Bl;
              float* Cf; __nv_bfloat16 *Ch, *Cl;
              const float* bias; int N, K, act; };
struct HJobs { HJob j[3]; };

#define LDK 40
#define AROWS 256
#define ASZ2 (AROWS*LDK)

__device__ __forceinline__ void ldm_x4(uint32_t addr, uint32_t r[4]) {
    asm volatile("ldmatrix.sync.aligned.m8n8.x4.shared.b16 {%0,%1,%2,%3}, [%4];"
        : "=r"(r[0]), "=r"(r[1]), "=r"(r[2]), "=r"(r[3]) : "r"(addr));
}
__device__ __forceinline__ void ldm_x2(uint32_t addr, uint32_t r[2]) {
    asm volatile("ldmatrix.sync.aligned.m8n8.x2.shared.b16 {%0,%1}, [%2];"
        : "=r"(r[0]), "=r"(r[1]) : "r"(addr));
}
__device__ __forceinline__ void mma_bf16(float* d, const uint32_t* a,
                                         const uint32_t* b) {
    asm volatile("mma.sync.aligned.m16n8k16.row.col.f32.bf16.bf16.f32 "
        "{%0,%1,%2,%3}, {%4,%5,%6,%7}, {%8,%9}, {%0,%1,%2,%3};"
        : "+f"(d[0]), "+f"(d[1]), "+f"(d[2]), "+f"(d[3])
        : "r"(a[0]), "r"(a[1]), "r"(a[2]), "r"(a[3]), "r"(b[0]), "r"(b[1]));
}

__device__ __forceinline__ void emit2(const HJob& jb, int row, int col,
                                      float v0, float v1)
{
    size_t idx = (size_t)row * jb.N + col;
    int act = jb.act;
    if (act == 0) {
        *(float2*)(jb.Cf + idx) = make_float2(v0, v1);
    } else if (act == 3) {
        float t0 = g_w0[col]   + v0 + jb.bias[col];
        float t1 = g_w0[col+1] + v1 + jb.bias[col+1];
        float n0 = -t0, n1 = -t1;
        float s0 = (n0 > 20.f) ? n0 : log1pf(expf(n0));
        float s1 = (n1 > 20.f) ? n1 : log1pf(expf(n1));
        *(float2*)(jb.Cf + idx) =
            make_float2(expf(-expf(-s0 - 0.5f)), expf(-expf(-s1 - 0.5f)));
    } else if (act == 5) {
        float y0 = 1.f / (1.f + expf(-(v0 + jb.bias[col])));
        float y1 = 1.f / (1.f + expf(-(v1 + jb.bias[col+1])));
        *(float2*)(jb.Cf + idx) = make_float2(y0, y1);
    } else {
        if (act == 1) { v0 = tanhf(v0); v1 = tanhf(v1); }
        else if (act == 2) {
            v0 = 1.f / (1.f + expf(-v0));
            v1 = 1.f / (1.f + expf(-v1));
        }
        uint32_t lov;
        uint32_t hiv = pack_bf2(v0, v1, lov);
        *(uint32_t*)(jb.Ch + idx) = hiv;
        *(uint32_t*)(jb.Cl + idx) = lov;
    }
}

template<int NT>
__global__ void __launch_bounds__(512, 1) hg3_kernel(HJobs jobs)
{
    HJob jb = jobs.j[blockIdx.z];
    const int N = jb.N, K = jb.K;
    const int m0 = blockIdx.y * AROWS;
    const int n0 = blockIdx.x * NT;
    if (n0 >= N) return;

    constexpr int BSZ  = NT * LDK;
    constexpr int STGE = 2*ASZ2 + 2*BSZ;
    constexpr int MTt  = (NT == 128) ? 4 : 2;

    extern __shared__ __nv_bfloat16 sm3[];
    uint32_t s0 = smem_u32(sm3);

    int tid  = threadIdx.x;
    int wid  = tid >> 5;
    int lane = tid & 31;
    int wm, wn;
    if (NT == 128) { wm = (wid & 3) * 64; wn = (wid >> 2) * 32; }
    else           { wm = (wid & 7) * 32; wn = (wid >> 3) * 32; }

    int alr = tid >> 1, alseg = tid & 1;
    const __nv_bfloat16* sAh = jb.Ah + (size_t)(m0 + alr) * K + alseg * 16;
    const __nv_bfloat16* sAl = jb.Al + (size_t)(m0 + alr) * K + alseg * 16;
    uint32_t aoff = (alr * LDK + alseg * 16) * 2;

    bool bthr = tid < NT*2;
    int brow = (tid >> 1) & (NT-1), bseg = tid & 1;
    bool bok = bthr && ((n0 + brow) < N);
    const __nv_bfloat16* sBh = jb.Bh + (size_t)(n0 + brow) * K + bseg * 16;
    const __nv_bfloat16* sBl = jb.Bl + (size_t)(n0 + brow) * K + bseg * 16;
    uint32_t boff = (2*ASZ2 + brow * LDK + bseg * 16) * 2;

    float acc[MTt][4][4];
#pragma unroll
    for (int i = 0; i < MTt; i++)
#pragma unroll
        for (int j = 0; j < 4; j++)
#pragma unroll
            for (int q = 0; q < 4; q++) acc[i][j][q] = 0.f;

    uint32_t rowA = (lane & 15) * (LDK*2);
    uint32_t colA = (lane >> 4) * 16;
    uint32_t rowB = (lane & 7)  * (LDK*2);
    uint32_t colB = ((lane >> 3) & 1) * 16;

    const int ncit = K >> 5;

#define HG3_ISSUE(c, st) do { \
        uint32_t dbase = s0 + (uint32_t)(st) * (STGE*2); \
        int adv = (c) * 32; \
        cp16(dbase + aoff,               sAh + adv); \
        cp16(dbase + aoff + 16,          sAh + adv + 8); \
        cp16(dbase + ASZ2*2 + aoff,      sAl + adv); \
        cp16(dbase + ASZ2*2 + aoff + 16, sAl + adv + 8); \
        if (bthr) { \
            cp16z(dbase + boff,               sBh + adv,     bok); \
            cp16z(dbase + boff + 16,          sBh + adv + 8, bok); \
            cp16z(dbase + BSZ*2 + boff,       sBl + adv,     bok); \
            cp16z(dbase + BSZ*2 + boff + 16,  sBl + adv + 8, bok); \
        } \
        asm volatile("cp.async.commit_group;"); \
    } while (0)

    HG3_ISSUE(0, 0);
    if (ncit > 1) HG3_ISSUE(1, 1);

    int st = 0;
    for (int c = 0; c < ncit; c++) {
        if (c + 1 < ncit)
            asm volatile("cp.async.wait_group 1;");
        else
            asm volatile("cp.async.wait_group 0;");
        __syncthreads();

        if (c + 2 < ncit) {
            int st2 = st + 2; if (st2 >= 3) st2 -= 3;
            HG3_ISSUE(c + 2, st2);
        }

        uint32_t sb    = s0 + (uint32_t)st * (STGE*2);
        uint32_t sAh_b = sb;
        uint32_t sAl_b = sb + ASZ2*2;
        uint32_t sBh_b = sb + 2*ASZ2*2;
        uint32_t sBl_b = sb + (2*ASZ2 + BSZ)*2;

#pragma unroll
        for (int ks = 0; ks < 2; ks++) {
            uint32_t bfh[4][2], bfl[4][2];
#pragma unroll
            for (int nt = 0; nt < 4; nt++) {
                uint32_t bo = (wn + nt*8) * (LDK*2) + rowB + ks*32 + colB;
                ldm_x2(sBh_b + bo, bfh[nt]);
                ldm_x2(sBl_b + bo, bfl[nt]);
            }
#pragma unroll
            for (int mt = 0; mt < MTt; mt++) {
                uint32_t afh[4], afl[4];
                uint32_t ao = (wm + mt*16) * (LDK*2) + rowA + ks*32 + colA;
                ldm_x4(sAh_b + ao, afh);
                ldm_x4(sAl_b + ao, afl);
#pragma unroll
                for (int nt = 0; nt < 4; nt++) {
                    mma_bf16(acc[mt][nt], afh, bfh[nt]);
                    mma_bf16(acc[mt][nt], afh, bfl[nt]);
                    mma_bf16(acc[mt][nt], afl, bfh[nt]);
                }
            }
        }
        if (++st == 3) st = 0;
    }
#undef HG3_ISSUE

    int g = lane >> 2, tg = lane & 3;
#pragma unroll
    for (int mt = 0; mt < MTt; mt++) {
#pragma unroll
        for (int nt = 0; nt < 4; nt++) {
            int cb = n0 + wn + nt*8 + 2*tg;
            if (cb >= N) continue;
            int r0 = m0 + wm + mt*16 + g;
            emit2(jb, r0,     cb, acc[mt][nt][0], acc[mt][nt][1]);
            emit2(jb, r0 + 8, cb, acc[mt][nt][2], acc[mt][nt][3]);
        }
    }
}

#define HS3_128 ((2*ASZ2 + 2*128*LDK) * 2 * 3)
#define HS3_64  ((2*ASZ2 + 2*64*LDK)  * 2 * 3)

// ---------------- kk normalize / a_in / b_in / k update --------------------
__global__ void kk_kernel(const float* __restrict__ kkc,
                          const float* __restrict__ kac)
{
    int gid  = blockIdx.x * blockDim.x + threadIdx.x;
    int lane = gid & 31;
    int grp  = gid >> 5;
    if (grp >= BT_*H_) return;
    int bt = grp / H_, h = grp % H_;
    int base = bt * C_ + h * D_;
    int c0   = h * D_;

    float k0v = g_k[base + lane],      k1v = g_k[base + 32 + lane];
    float a0  = g_a[base + lane],      a1  = g_a[base + 32 + lane];
    float kk0 = k0v * kkc[c0 + lane],  kk1 = k1v * kkc[c0 + 32 + lane];

    float ss = kk0*kk0 + kk1*kk1;
#pragma unroll
    for (int o = 16; o; o >>= 1) ss += __shfl_xor_sync(0xffffffffu, ss, o);
    float inv = 1.f / fmaxf(sqrtf(ss), 1e-12f);
    kk0 *= inv; kk1 *= inv;

    g_ain[base + lane]      = -kk0;
    g_ain[base + 32 + lane] = -kk1;
    g_bin[base + lane]      = kk0 * a0;
    g_bin[base + 32 + lane] = kk1 * a1;
    g_k[base + lane]        = k0v * (1.f + (a0 - 1.f) * kac[c0 + lane]);
    g_k[base + 32 + lane]   = k1v * (1.f + (a1 - 1.f) * kac[c0 + 32 + lane]);
}

// ---------------- RWKV-7 recurrence (v4 + RCHUNK 16, dynamic smem) ----------
__global__ void __launch_bounds__(128, 1) rec_kernel()
{
    int blk = blockIdx.x;
    int bh  = blk >> 2;
    int rb  = blk & 3;
    int b = bh >> 4, h = bh & 15;
    size_t base = (size_t)b * T_ * C_ + h * D_;

    extern __shared__ float rsm[];   // [2][6][RCHUNK][64] = 96 KB

    int tid = threadIdx.x;
    int row = rb * RROWS + (tid >> 3);
    int cp  = tid & 7;
    int c0  = cp * 8;

    // loaders: 6 vecs x RCHUNK steps x 16 quads = 1536 float4 / 128 thr = 12
    const float* srcs[6] = { g_r, g_decay, g_k, g_v, g_ain, g_bin };
    const float* gp[12];
    uint32_t sp_[12];
#pragma unroll
    for (int it = 0; it < 12; it++) {
        int f  = tid + it * 128;
        int q  = f & 15;
        int st = (f >> 4) & (RCHUNK-1);
        int vc = f >> 8;               // 16*RCHUNK = 256 slots per vec
        gp[it]  = srcs[vc] + base + (size_t)st * C_ + q * 4;
        sp_[it] = (uint32_t)((vc * RCHUNK + st) * 64 + q * 4);
    }

    unsigned long long S[4] = {0ull, 0ull, 0ull, 0ull};

    float4 pf[12];
#pragma unroll
    for (int it = 0; it < 12; it++) pf[it] = *(const float4*)gp[it];

    const int NCH = T_ / RCHUNK;
    for (int ch = 0; ch < NCH; ch++) {
        float* buf = rsm + (ch & 1) * (6*RCHUNK*64);
#pragma unroll
        for (int it = 0; it < 12; it++)
            *(float4*)(buf + sp_[it]) = pf[it];
        __syncthreads();
        if (ch + 1 < NCH) {
            size_t adv = (size_t)(ch + 1) * RCHUNK * C_;
#pragma unroll
            for (int it = 0; it < 12; it++)
                pf[it] = *(const float4*)(gp[it] + adv);
        }

        size_t obase = base + (size_t)ch * RCHUNK * C_ + row;
#pragma unroll 2
        for (int s = 0; s < RCHUNK; s++) {
            const float* rv = buf + (0*RCHUNK + s) * 64;
            const float* wv = buf + (1*RCHUNK + s) * 64;
            const float* kv = buf + (2*RCHUNK + s) * 64;
            const float* vv = buf + (3*RCHUNK + s) * 64;
            const float* av = buf + (4*RCHUNK + s) * 64;
            const float* bv = buf + (5*RCHUNK + s) * 64;

            ulonglong2 aA = *(const ulonglong2*)(av + c0);
            ulonglong2 aB = *(const ulonglong2*)(av + c0 + 4);
            unsigned long long sacc = f32x2_fma(S[0], aA.x, 0ull);
            sacc = f32x2_fma(S[1], aA.y, sacc);
            sacc = f32x2_fma(S[2], aB.x, sacc);
            sacc = f32x2_fma(S[3], aB.y, sacc);
            float2 spp = f32x2_unpack(sacc);
            float sa = spp.x + spp.y;
            sa += __shfl_xor_sync(0xffffffffu, sa, 1);
            sa += __shfl_xor_sync(0xffffffffu, sa, 2);
            sa += __shfl_xor_sync(0xffffffffu, sa, 4);

            float vj = vv[row];
            ulonglong2 wA = *(const ulonglong2*)(wv + c0);
            ulonglong2 wB = *(const ulonglong2*)(wv + c0 + 4);
            ulonglong2 bA = *(const ulonglong2*)(bv + c0);
            ulonglong2 bB = *(const ulonglong2*)(bv + c0 + 4);
            ulonglong2 kA = *(const ulonglong2*)(kv + c0);
            ulonglong2 kB = *(const ulonglong2*)(kv + c0 + 4);
            ulonglong2 rA = *(const ulonglong2*)(rv + c0);
            ulonglong2 rB = *(const ulonglong2*)(rv + c0 + 4);

            unsigned long long sa2 = f32x2_pack(sa, sa);
            unsigned long long v2  = f32x2_pack(vj, vj);

            S[0] = f32x2_fma(v2, kA.x, f32x2_fma(sa2, bA.x, f32x2_fma(S[0], wA.x, 0ull)));
            S[1] = f32x2_fma(v2, kA.y, f32x2_fma(sa2, bA.y, f32x2_fma(S[1], wA.y, 0ull)));
            S[2] = f32x2_fma(v2, kB.x, f32x2_fma(sa2, bB.x, f32x2_fma(S[2], wB.x, 0ull)));
            S[3] = f32x2_fma(v2, kB.y, f32x2_fma(sa2, bB.y, f32x2_fma(S[3], wB.y, 0ull)));

            unsigned long long oacc = f32x2_fma(S[0], rA.x, 0ull);
            oacc = f32x2_fma(S[1], rA.y, oacc);
            oacc = f32x2_fma(S[2], rB.x, oacc);
            oacc = f32x2_fma(S[3], rB.y, oacc);
            float2 op = f32x2_unpack(oacc);
            float o = op.x + op.y;
            o += __shfl_xor_sync(0xffffffffu, o, 1);
            o += __shfl_xor_sync(0xffffffffu, o, 2);
            o += __shfl_xor_sync(0xffffffffu, o, 4);
            if (cp == 0) g_o[obase + (size_t)s * C_] = o;
        }
    }
}
#define RSMEM_BYTES (2*6*RCHUNK*64*4)   // 98304

// ---------------- GroupNorm + bonus + gate (emits bf16 hi/lo) --------------
__global__ void post_kernel(const float* __restrict__ rk,
                            const float* __restrict__ gnw,
                            const float* __restrict__ gnb)
{
    int gid  = blockIdx.x * blockDim.x + threadIdx.x;
    int lane = gid & 31;
    int grp  = gid >> 5;
    if (grp >= BT_*H_) return;
    int bt = grp / H_, h = grp % H_;
    int base = bt * C_ + h * D_;
    int c0   = h * D_;

    float o0 = g_o[base + lane], o1 = g_o[base + 32 + lane];
    float su = o0 + o1;
    float sq = o0*o0 + o1*o1;
    float r0 = g_r[base + lane], r1 = g_r[base + 32 + lane];
    float k0 = g_k[base + lane], k1 = g_k[base + 32 + lane];
    float bsum = r0*k0*rk[c0 + lane] + r1*k1*rk[c0 + 32 + lane];
#pragma unroll
    for (int o = 16; o; o >>= 1) {
        su   += __shfl_xor_sync(0xffffffffu, su,   o);
        sq   += __shfl_xor_sync(0xffffffffu, sq,   o);
        bsum += __shfl_xor_sync(0xffffffffu, bsum, o);
    }
    float mu  = su / 64.f;
    float var = sq / 64.f - mu * mu;
    float inv = rsqrtf(var + EPS_);

    float v0 = g_v[base + lane], v1 = g_v[base + 32 + lane];
    float on0 = (o0 - mu) * inv * gnw[c0 + lane]      + gnb[c0 + lane];
    float on1 = (o1 - mu) * inv * gnw[c0 + 32 + lane] + gnb[c0 + 32 + lane];
    float p0 = (on0 + bsum * v0) * g_g[base + lane];
    float p1 = (on1 + bsum * v1) * g_g[base + 32 + lane];

    __nv_bfloat16 h0 = __float2bfloat16_rn(p0);
    __nv_bfloat16 h1 = __float2bfloat16_rn(p1);
    g_preh[base + lane]      = h0;
    g_preh[base + 32 + lane] = h1;
    g_prel[base + lane]      = __float2bfloat16_rn(p0 - __bfloat162float(h0));
    g_prel[base + 32 + lane] = __float2bfloat16_rn(p1 - __bfloat162float(h1));
}

// ---------------- host launcher ---------------------------------------------
extern "C" void kernel_launch(void* const* d_in, const int* in_sizes, int n_in,
                              void* d_out, int out_size)
{
    const float* x        = (const float*)d_in[0];
    const float* x_r      = (const float*)d_in[1];
    const float* x_w      = (const float*)d_in[2];
    const float* x_k      = (const float*)d_in[3];
    const float* x_v      = (const float*)d_in[4];
    const float* x_a      = (const float*)d_in[5];
    const float* x_g      = (const float*)d_in[6];
    const float* k_k      = (const float*)d_in[7];
    const float* k_a      = (const float*)d_in[8];
    const float* r_k      = (const float*)d_in[9];
    const float* Wr       = (const float*)d_in[10];
    const float* Wk       = (const float*)d_in[11];
    const float* Wv       = (const float*)d_in[12];
    const float* Wo       = (const float*)d_in[13];
    const float* wA       = (const float*)d_in[14];
    const float* wB       = (const float*)d_in[15];
    const float* wBias    = (const float*)d_in[16];
    const float* aA       = (const float*)d_in[17];
    const float* aB       = (const float*)d_in[18];
    const float* aBias    = (const float*)d_in[19];
    const float* gA       = (const float*)d_in[20];
    const float* gB       = (const float*)d_in[21];
    const float* gnw      = (const float*)d_in[22];
    const float* gnb      = (const float*)d_in[23];
    const float* w0_base  = (const float*)d_in[24];
    const float* w0_delta = (const float*)d_in[25];
    float* out = (float*)d_out;

#define SYM(p, s) cudaGetSymbolAddress((void**)&p, s)
    float *p_r,*p_k,*p_v,*p_dec,*p_a,*p_g;
    __nv_bfloat16 *p_xrh,*p_xrl,*p_xkh,*p_xkl,*p_xvh,*p_xvl;
    __nv_bfloat16 *p_xwh,*p_xwl,*p_xah,*p_xal,*p_xgh,*p_xgl;
    __nv_bfloat16 *p_preh,*p_prel,*p_wh,*p_wl;
    __nv_bfloat16 *p_wAh,*p_wAl,*p_aAh,*p_aAl,*p_gAh,*p_gAl;
    __nv_bfloat16 *p_wBh,*p_wBl,*p_aBh,*p_aBl,*p_gBh,*p_gBl;
    __nv_bfloat16 *p_w1h,*p_w1l,*p_a1h,*p_a1l,*p_g1h,*p_g1l;
    SYM(p_r, g_r); SYM(p_k, g_k); SYM(p_v, g_v);
    SYM(p_dec, g_decay); SYM(p_a, g_a); SYM(p_g, g_g);
    SYM(p_xrh, g_xrh); SYM(p_xrl, g_xrl);
    SYM(p_xkh, g_xkh); SYM(p_xkl, g_xkl);
    SYM(p_xvh, g_xvh); SYM(p_xvl, g_xvl);
    SYM(p_xwh, g_xwh); SYM(p_xwl, g_xwl);
    SYM(p_xah, g_xah); SYM(p_xal, g_xal);
    SYM(p_xgh, g_xgh); SYM(p_xgl, g_xgl);
    SYM(p_preh, g_preh); SYM(p_prel, g_prel);
    SYM(p_wh, g_wh); SYM(p_wl, g_wl);
    SYM(p_wAh, g_wAh); SYM(p_wAl, g_wAl);
    SYM(p_aAh, g_aAh); SYM(p_aAl, g_aAl);
    SYM(p_gAh, g_gAh); SYM(p_gAl, g_gAl);
    SYM(p_wBh, g_wBh); SYM(p_wBl, g_wBl);
    SYM(p_aBh, g_aBh); SYM(p_aBl, g_aBl);
    SYM(p_gBh, g_gBh); SYM(p_gBl, g_gBl);
    SYM(p_w1h, g_w1h); SYM(p_w1l, g_w1l);
    SYM(p_a1h, g_a1h); SYM(p_a1l, g_a1l);
    SYM(p_g1h, g_g1h); SYM(p_g1l, g_g1l);
#undef SYM

    cudaFuncSetAttribute(hg3_kernel<128>,
        cudaFuncAttributeMaxDynamicSharedMemorySize, HS3_128);
    cudaFuncSetAttribute(hg3_kernel<64>,
        cudaFuncAttributeMaxDynamicSharedMemorySize, HS3_64);
    cudaFuncSetAttribute(rec_kernel,
        cudaFuncAttributeMaxDynamicSharedMemorySize, RSMEM_BYTES);

    // 0) all weights fp32 -> bf16 hi/lo
    {
        WcJobs wj;
        wj.j[0] = { Wr, p_wh + 0*C_*C_, p_wl + 0*C_*C_, C_*C_ };
        wj.j[1] = { Wk, p_wh + 1*C_*C_, p_wl + 1*C_*C_, C_*C_ };
        wj.j[2] = { Wv, p_wh + 2*C_*C_, p_wl + 2*C_*C_, C_*C_ };
        wj.j[3] = { Wo, p_wh + 3*C_*C_, p_wl + 3*C_*C_, C_*C_ };
        wj.j[4] = { wA, p_wAh, p_wAl, RW_*C_ };
        wj.j[5] = { aA, p_aAh, p_aAl, RA_*C_ };
        wj.j[6] = { gA, p_gAh, p_gAl, RG_*C_ };
        wj.j[7] = { wB, p_wBh, p_wBl, C_*RW_ };
        wj.j[8] = { aB, p_aBh, p_aBl, C_*RA_ };
        wj.j[9] = { gB, p_gBh, p_gBl, C_*RG_ };
        wconv_kernel<<<dim3(C_*C_/4/256, 10), 256>>>(wj);
    }

    // 1) token-shift mixes -> bf16 hi/lo (all six)
    mix_kernel<<<(BT_*C_/4 + 255)/256, 256>>>(x, x_r, x_w, x_k, x_v, x_a, x_g);

    // 2) w0 scan
    w0_kernel<<<1, C_>>>(w0_base, w0_delta);

    // 3) r/k/v projections (HMMA 256x128, 3-stage cp.async)
    {
        HJobs hj;
        hj.j[0] = { p_xrh, p_xrl, p_wh + 0*C_*C_, p_wl + 0*C_*C_,
                    p_r, nullptr, nullptr, nullptr, C_, C_, 0 };
        hj.j[1] = { p_xkh, p_xkl, p_wh + 1*C_*C_, p_wl + 1*C_*C_,
                    p_k, nullptr, nullptr, nullptr, C_, C_, 0 };
        hj.j[2] = { p_xvh, p_xvl, p_wh + 2*C_*C_, p_wl + 2*C_*C_,
                    p_v, nullptr, nullptr, nullptr, C_, C_, 0 };
        hg3_kernel<128><<<dim3(C_/128, BT_/AROWS, 3), 512, HS3_128>>>(hj);
    }

    // 4) LoRA stage 1 (NT=64, epilogue emits bf16 hi/lo)
    {
        HJobs hj;
        hj.j[0] = { p_xwh, p_xwl, p_wAh, p_wAl,
                    nullptr, p_w1h, p_w1l, nullptr, RW_, C_, 1 };   // tanh
        hj.j[1] = { p_xah, p_xal, p_aAh, p_aAl,
                    nullptr, p_a1h, p_a1l, nullptr, RA_, C_, 6 };   // none
        hj.j[2] = { p_xgh, p_xgl, p_gAh, p_gAl,
                    nullptr, p_g1h, p_g1l, nullptr, RG_, C_, 2 };   // sigmoid
        hg3_kernel<64><<<dim3((RG_+63)/64, BT_/AROWS, 3), 512, HS3_64>>>(hj);
    }

    // 5) LoRA stage 2 (NT=128, fused epilogues)
    {
        HJobs hj;
        hj.j[0] = { p_w1h, p_w1l, p_wBh, p_wBl,
                    p_dec, nullptr, nullptr, wBias, C_, RW_, 3 };   // decay
        hj.j[1] = { p_a1h, p_a1l, p_aBh, p_aBl,
                    p_a, nullptr, nullptr, aBias, C_, RA_, 5 };     // sigm+bias
        hj.j[2] = { p_g1h, p_g1l, p_gBh, p_gBl,
                    p_g, nullptr, nullptr, nullptr, C_, RG_, 0 };
        hg3_kernel<128><<<dim3(C_/128, BT_/AROWS, 3), 512, HS3_128>>>(hj);
    }

    // 6) kk normalize / a_in / b_in / k update
    kk_kernel<<<(BT_*H_*32 + 255)/256, 256>>>(k_k, k_a);

    // 7) sequential recurrence (v4 layout, RCHUNK=16, dynamic smem)
    rec_kernel<<<128, 128, RSMEM_BYTES>>>();

    // 8) GroupNorm + bonus + gate (-> bf16 hi/lo)
    post_kernel<<<(BT_*H_*32 + 255)/256, 256>>>(r_k, gnw, gnb);

    // 9) output projection (HMMA)
    {
        HJobs hj;
        hj.j[0] = { p_preh, p_prel, p_wh + 3*C_*C_, p_wl + 3*C_*C_,
                    out, nullptr, nullptr, nullptr, C_, C_, 0 };
        hj.j[1] = hj.j[0];
        hj.j[2] = hj.j[0];
        hg3_kernel<128><<<dim3(C_/128, BT_/AROWS, 1), 512, HS3_128>>>(hj);
    }
}